// round 1
// baseline (speedup 1.0000x reference)
#include <cuda_runtime.h>
#include <math.h>

// ---------------- problem constants ----------------
#define NVB   6        // V*B sequences
#define VV    3
#define BB    2
#define CC    256      // channels
#define LTOK  1024     // tokens per view (32*32)
#define TKX   2048     // max kv tokens (cross: (V-1)*L)
#define NH    4        // heads
#define HD    64       // head dim
#define FFNI  512
#define FFNH  2048

// ---------------- device scratch (no allocations allowed) ----------------
__device__ float g_x   [NVB*LTOK*CC];
__device__ float g_xpre[NVB*LTOK*CC];
__device__ float g_q   [NVB*LTOK*CC];
__device__ float g_k   [NVB*LTOK*CC];
__device__ float g_v   [NVB*LTOK*CC];
__device__ float g_qp  [NVB*NH*LTOK*HD];
__device__ float g_kp  [NVB*NH*TKX*HD];
__device__ float g_vp  [NVB*NH*TKX*HD];
__device__ float g_S   [(size_t)NVB*NH*LTOK*TKX];   // 50.3M floats
__device__ float g_O   [NVB*NH*LTOK*HD];
__device__ float g_om  [NVB*LTOK*CC];
__device__ float g_msg [NVB*LTOK*CC];
__device__ float g_cat [NVB*LTOK*FFNI];
__device__ float g_h   [NVB*LTOK*FFNH];
__device__ float g_h2  [NVB*LTOK*CC];
__device__ float g_Mq  [NVB*LTOK*16];
__device__ float g_Mqi [NVB*LTOK*16];
__device__ float g_Mkv [NVB*TKX*16];

// ---------------- layout kernels ----------------
// features [n][c][l] -> x [n][l][c]
__global__ void k_build_x(const float* __restrict__ f, float* __restrict__ x) {
    int idx = blockIdx.x * blockDim.x + threadIdx.x;        // over n*l*c, c fastest
    if (idx >= NVB*LTOK*CC) return;
    int c = idx & (CC-1);
    int l = (idx >> 8) & (LTOK-1);
    int n = idx >> 18;
    x[idx] = f[((size_t)n*CC + c)*LTOK + l];
}

// x [n][l][c] -> out [n][c][l]
__global__ void k_final(const float* __restrict__ x, float* __restrict__ o) {
    int idx = blockIdx.x * blockDim.x + threadIdx.x;        // over n*c*l, l fastest
    if (idx >= NVB*LTOK*CC) return;
    int l = idx & (LTOK-1);
    int c = (idx >> 10) & (CC-1);
    int n = idx >> 18;
    o[idx] = x[((size_t)n*LTOK + l)*CC + c];
}

__global__ void k_copy(float* __restrict__ d, const float* __restrict__ s, int nelem) {
    int i = blockIdx.x * blockDim.x + threadIdx.x;
    if (i < nelem) d[i] = s[i];
}

// ---------------- PRoPE matrix build ----------------
__device__ __forceinline__ void prope_forward(const float* vm, const float* Kc,
                                              float u, float vyy, float* M) {
    float fx = Kc[0] * (1.0f/128.0f), fy = Kc[4] * (1.0f/128.0f);
    float cx = Kc[2] * (1.0f/128.0f), cy = Kc[5] * (1.0f/128.0f);
    float a = cx - u, b = cy - vyy;
    #pragma unroll
    for (int c = 0; c < 4; c++) {
        M[0*4+c] = fx*vm[0*4+c] + a*vm[2*4+c];
        M[1*4+c] = fy*vm[1*4+c] + b*vm[2*4+c];
        M[2*4+c] = vm[2*4+c];
        M[3*4+c] = vm[3*4+c];
    }
}

__global__ void k_prope_q(const float* __restrict__ vms, const float* __restrict__ Ks,
                          float* __restrict__ Mq, float* __restrict__ Mqi) {
    int idx = blockIdx.x * blockDim.x + threadIdx.x;
    if (idx >= NVB*LTOK) return;
    int n = idx >> 10, t = idx & (LTOK-1);
    int px = t & 31, py = t >> 5;
    float u  = (px + 0.5f) * (1.0f/32.0f);
    float vy = (py + 0.5f) * (1.0f/32.0f);
    const float* vm = vms + n*16;
    const float* Kc = Ks + n*9;
    float M[16];
    prope_forward(vm, Kc, u, vy, M);
    #pragma unroll
    for (int i = 0; i < 16; i++) Mq[idx*16+i] = M[i];

    // inverse: (T vm)^-1 = vm^-1 T^-1, vm = [[R,t],[0,1]]
    float r00=vm[0],r01=vm[1],r02=vm[2],  t0=vm[3];
    float r10=vm[4],r11=vm[5],r12=vm[6],  t1=vm[7];
    float r20=vm[8],r21=vm[9],r22=vm[10], t2=vm[11];
    float det = r00*(r11*r22-r12*r21) - r01*(r10*r22-r12*r20) + r02*(r10*r21-r11*r20);
    float id = 1.0f/det;
    float Ri[9];
    Ri[0]=(r11*r22-r12*r21)*id; Ri[1]=(r02*r21-r01*r22)*id; Ri[2]=(r01*r12-r02*r11)*id;
    Ri[3]=(r12*r20-r10*r22)*id; Ri[4]=(r00*r22-r02*r20)*id; Ri[5]=(r02*r10-r00*r12)*id;
    Ri[6]=(r10*r21-r11*r20)*id; Ri[7]=(r01*r20-r00*r21)*id; Ri[8]=(r00*r11-r01*r10)*id;
    float ti0 = -(Ri[0]*t0 + Ri[1]*t1 + Ri[2]*t2);
    float ti1 = -(Ri[3]*t0 + Ri[4]*t1 + Ri[5]*t2);
    float ti2 = -(Ri[6]*t0 + Ri[7]*t1 + Ri[8]*t2);
    float fx = Kc[0]*(1.0f/128.0f), fy = Kc[4]*(1.0f/128.0f);
    float cx = Kc[2]*(1.0f/128.0f), cy = Kc[5]*(1.0f/128.0f);
    float a = cx - u, b = cy - vy;
    float ifx = 1.0f/fx, ify = 1.0f/fy;
    float Mi[16];
    float tv[3] = {ti0, ti1, ti2};
    #pragma unroll
    for (int i = 0; i < 3; i++) {
        Mi[i*4+0] = Ri[i*3+0]*ifx;
        Mi[i*4+1] = Ri[i*3+1]*ify;
        Mi[i*4+2] = -Ri[i*3+0]*a*ifx - Ri[i*3+1]*b*ify + Ri[i*3+2];
        Mi[i*4+3] = tv[i];
    }
    Mi[12]=0.f; Mi[13]=0.f; Mi[14]=0.f; Mi[15]=1.f;
    #pragma unroll
    for (int i = 0; i < 16; i++) Mqi[idx*16+i] = Mi[i];
}

__global__ void k_prope_kv(const float* __restrict__ vms, const float* __restrict__ Ks,
                           float* __restrict__ Mkv) {
    int idx = blockIdx.x * blockDim.x + threadIdx.x;
    if (idx >= NVB*TKX) return;
    int n = idx >> 11, tt = idx & (TKX-1);
    int m = tt >> 10, l = tt & (LTOK-1);
    int vvi = n >> 1, b = n & 1;
    int j = m + (m >= vvi ? 1 : 0);           // IDX[v][m]
    int cam = j*BB + b;
    int px = l & 31, py = l >> 5;
    float u  = (px + 0.5f)*(1.0f/32.0f);
    float vy = (py + 0.5f)*(1.0f/32.0f);
    float M[16];
    prope_forward(vms + cam*16, Ks + cam*9, u, vy, M);
    #pragma unroll
    for (int i = 0; i < 16; i++) Mkv[idx*16+i] = M[i];
}

// ---------------- generic tiled GEMM: C = alpha * A @ op(B) ----------------
// BT=true : B is [N,K] row-major (C = A B^T).  BT=false: B is [K,N] row-major.
// A: [M,K] row-major, lda=K. ldc=N. All of M%64==0, N%64==0, K%16==0 guaranteed.
template<bool BT>
__global__ void k_gemm(const float* __restrict__ A, const float* __restrict__ B,
                       float* __restrict__ C, int M, int N, int K,
                       long long sA, long long sB, long long sC, float alpha)
{
    constexpr int BM = 64, BN = 64, BK = 16;
    __shared__ float As[BK][BM+4];
    __shared__ float Bs[BK][BN+4];
    A += (long long)blockIdx.z * sA;
    B += (long long)blockIdx.z * sB;
    C += (long long)blockIdx.z * sC;
    const int m0 = blockIdx.y * BM, n0 = blockIdx.x * BN;
    const int tid = threadIdx.x;
    const int tx = tid & 15, ty = tid >> 4;
    float acc[4][4] = {};
    for (int k0 = 0; k0 < K; k0 += BK) {
        {   // A tile: 64 rows x 16 k, float4 along K
            int i = tid * 4;
            int m = i >> 4, k = i & 15;
            float4 av = *reinterpret_cast<const float4*>(&A[(long long)(m0+m)*K + k0 + k]);
            As[k+0][m]=av.x; As[k+1][m]=av.y; As[k+2][m]=av.z; As[k+3][m]=av.w;
        }
        if (BT) {
            int i = tid * 4;
            int n = i >> 4, k = i & 15;
            float4 bv = *reinterpret_cast<const float4*>(&B[(long long)(n0+n)*K + k0 + k]);
            Bs[k+0][n]=bv.x; Bs[k+1][n]=bv.y; Bs[k+2][n]=bv.z; Bs[k+3][n]=bv.w;
        } else {
            int i = tid * 4;
            int k = i >> 6, n = i & 63;
            float4 bv = *reinterpret_cast<const float4*>(&B[(long long)(k0+k)*N + n0 + n]);
            Bs[k][n+0]=bv.x; Bs[k][n+1]=bv.y; Bs[k][n+2]=bv.z; Bs[k][n+3]=bv.w;
        }
        __syncthreads();
        #pragma unroll
        for (int kk = 0; kk < BK; kk++) {
            float a[4], b[4];
            #pragma unroll
            for (int i = 0; i < 4; i++) a[i] = As[kk][ty*4+i];
            #pragma unroll
            for (int j = 0; j < 4; j++) b[j] = Bs[kk][tx*4+j];
            #pragma unroll
            for (int i = 0; i < 4; i++)
                #pragma unroll
                for (int j = 0; j < 4; j++)
                    acc[i][j] += a[i]*b[j];
        }
        __syncthreads();
    }
    #pragma unroll
    for (int i = 0; i < 4; i++)
        #pragma unroll
        for (int j = 0; j < 4; j++)
            C[(long long)(m0+ty*4+i)*N + n0 + tx*4 + j] = alpha * acc[i][j];
}

// ---------------- per-token 4x4 projective applies ----------------
// qp[n][h][t][d] = sum_j Mqi[n][t][j][i] * q[n][t][h*64+g*4+j]   (M^T apply)
__global__ void k_apply_q(const float* __restrict__ q, const float* __restrict__ Mi,
                          float* __restrict__ qp) {
    int idx = blockIdx.x * blockDim.x + threadIdx.x;     // n*t*h*g = 6*1024*4*16
    if (idx >= NVB*LTOK*NH*16) return;
    int g = idx & 15, h = (idx >> 4) & 3, t = (idx >> 6) & (LTOK-1), n = idx >> 16;
    const float* M = Mi + ((size_t)(n*LTOK + t))*16;
    const float* s = q + ((size_t)(n*LTOK + t))*CC + h*HD + g*4;
    float x0=s[0], x1=s[1], x2=s[2], x3=s[3];
    float* d = qp + (((size_t)(n*NH + h))*LTOK + t)*HD + g*4;
    #pragma unroll
    for (int i = 0; i < 4; i++)
        d[i] = M[0*4+i]*x0 + M[1*4+i]*x1 + M[2*4+i]*x2 + M[3*4+i]*x3;
}

// kp[n][h][tt][d] = Mkv[n][tt] @ k_src[srcRow][h*64+g*4 .. ]
// gather=0: srcRow = n*L + tt (self).  gather=1: cross, tt = m*L+l, src view = IDX[v][m]
__global__ void k_apply_kv(const float* __restrict__ ks, const float* __restrict__ Mats,
                           float* __restrict__ kp, int Tk, int gather) {
    int idx = blockIdx.x * blockDim.x + threadIdx.x;     // n*Tk*4*16
    if (idx >= NVB*Tk*NH*16) return;
    int g = idx & 15, h = (idx >> 4) & 3;
    int tt = (idx >> 6) % Tk, n = (idx >> 6) / Tk;
    size_t srcRow;
    if (gather) {
        int m = tt >> 10, l = tt & (LTOK-1);
        int vvi = n >> 1, b = n & 1;
        int j = m + (m >= vvi ? 1 : 0);
        srcRow = (size_t)(j*BB + b)*LTOK + l;
    } else {
        srcRow = (size_t)n*LTOK + tt;
    }
    const float* M = Mats + ((size_t)n*Tk + tt)*16;
    const float* s = ks + srcRow*CC + h*HD + g*4;
    float x0=s[0], x1=s[1], x2=s[2], x3=s[3];
    float* d = kp + (((size_t)(n*NH + h))*Tk + tt)*HD + g*4;
    #pragma unroll
    for (int i = 0; i < 4; i++)
        d[i] = M[i*4+0]*x0 + M[i*4+1]*x1 + M[i*4+2]*x2 + M[i*4+3]*x3;
}

// om[n][t][h*64+d] = Mqi[n][t] @ O[n][h][t][..]   (merge heads)
__global__ void k_apply_out(const float* __restrict__ O, const float* __restrict__ Mi,
                            float* __restrict__ om) {
    int idx = blockIdx.x * blockDim.x + threadIdx.x;
    if (idx >= NVB*LTOK*NH*16) return;
    int g = idx & 15, h = (idx >> 4) & 3, t = (idx >> 6) & (LTOK-1), n = idx >> 16;
    const float* M = Mi + ((size_t)(n*LTOK + t))*16;
    const float* s = O + (((size_t)(n*NH + h))*LTOK + t)*HD + g*4;
    float x0=s[0], x1=s[1], x2=s[2], x3=s[3];
    float* d = om + ((size_t)(n*LTOK + t))*CC + h*HD + g*4;
    #pragma unroll
    for (int i = 0; i < 4; i++)
        d[i] = M[i*4+0]*x0 + M[i*4+1]*x1 + M[i*4+2]*x2 + M[i*4+3]*x3;
}

// ---------------- softmax over rows of S (row length Tk, Tk%256==0) ----------------
__global__ void k_softmax(float* __restrict__ S, int Tk) {
    float* row = S + (size_t)blockIdx.x * Tk;
    int tid = threadIdx.x;
    int nv = Tk >> 8;
    float vals[8];
    float mx = -1e30f;
    for (int i = 0; i < nv; i++) { vals[i] = row[tid + (i<<8)]; mx = fmaxf(mx, vals[i]); }
    __shared__ float red[256];
    red[tid] = mx; __syncthreads();
    for (int s = 128; s > 0; s >>= 1) { if (tid < s) red[tid] = fmaxf(red[tid], red[tid+s]); __syncthreads(); }
    mx = red[0]; __syncthreads();
    float sum = 0.f;
    for (int i = 0; i < nv; i++) { vals[i] = __expf(vals[i] - mx); sum += vals[i]; }
    red[tid] = sum; __syncthreads();
    for (int s = 128; s > 0; s >>= 1) { if (tid < s) red[tid] += red[tid+s]; __syncthreads(); }
    float inv = 1.0f / red[0];
    for (int i = 0; i < nv; i++) row[tid + (i<<8)] = vals[i] * inv;
}

// ---------------- layernorm (C=256, one row/block, one elem/thread) ----------------
__global__ void k_ln(float* __restrict__ dst, const float* __restrict__ src,
                     const float* __restrict__ w, const float* __restrict__ b, int add) {
    __shared__ float red[256];
    int row = blockIdx.x, tid = threadIdx.x;
    float v = src[(size_t)row*CC + tid];
    red[tid] = v; __syncthreads();
    for (int s = 128; s > 0; s >>= 1) { if (tid < s) red[tid] += red[tid+s]; __syncthreads(); }
    float mu = red[0] * (1.0f/CC); __syncthreads();
    float d = v - mu;
    red[tid] = d * d; __syncthreads();
    for (int s = 128; s > 0; s >>= 1) { if (tid < s) red[tid] += red[tid+s]; __syncthreads(); }
    float var = red[0] * (1.0f/CC);
    float o = d * rsqrtf(var + 1e-5f) * w[tid] + b[tid];
    if (add) dst[(size_t)row*CC + tid] += o;
    else     dst[(size_t)row*CC + tid] = o;
}

// ---------------- misc elementwise ----------------
__global__ void k_cat(const float* __restrict__ x, const float* __restrict__ msg,
                      float* __restrict__ cat) {
    int idx = blockIdx.x * blockDim.x + threadIdx.x;     // rows*512
    if (idx >= NVB*LTOK*FFNI) return;
    int c = idx & 511, row = idx >> 9;
    cat[idx] = (c < CC) ? x[(size_t)row*CC + c] : msg[(size_t)row*CC + c - CC];
}

__global__ void k_gelu(float* __restrict__ h, int nelem) {
    int i = blockIdx.x * blockDim.x + threadIdx.x;
    if (i < nelem) {
        float v = h[i];
        h[i] = 0.5f * v * (1.0f + erff(v * 0.70710678118654752f));
    }
}

// ---------------- host driver ----------------
static inline dim3 gg(int M, int N, int batch) { return dim3(N/64, M/64, batch); }

extern "C" void kernel_launch(void* const* d_in, const int* in_sizes, int n_in,
                              void* d_out, int out_size) {
    const float* feats = (const float*)d_in[0];
    const float* vms   = (const float*)d_in[1];
    const float* Ks    = (const float*)d_in[2];
    const float* Wq    = (const float*)d_in[3];
    const float* Wk    = (const float*)d_in[4];
    const float* Wv    = (const float*)d_in[5];
    const float* Wm    = (const float*)d_in[6];
    const float* n1w   = (const float*)d_in[7];
    const float* n1b   = (const float*)d_in[8];
    const float* W1    = (const float*)d_in[9];
    const float* W2    = (const float*)d_in[10];
    const float* n2w   = (const float*)d_in[11];
    const float* n2b   = (const float*)d_in[12];

    void* p;
    float *x,*xpre,*q,*k,*v,*qp,*kp,*vp,*S,*O,*om,*msg,*cat,*h,*h2,*Mq,*Mqi,*Mkv;
    cudaGetSymbolAddress(&p, g_x);    x   = (float*)p;
    cudaGetSymbolAddress(&p, g_xpre); xpre= (float*)p;
    cudaGetSymbolAddress(&p, g_q);    q   = (float*)p;
    cudaGetSymbolAddress(&p, g_k);    k   = (float*)p;
    cudaGetSymbolAddress(&p, g_v);    v   = (float*)p;
    cudaGetSymbolAddress(&p, g_qp);   qp  = (float*)p;
    cudaGetSymbolAddress(&p, g_kp);   kp  = (float*)p;
    cudaGetSymbolAddress(&p, g_vp);   vp  = (float*)p;
    cudaGetSymbolAddress(&p, g_S);    S   = (float*)p;
    cudaGetSymbolAddress(&p, g_O);    O   = (float*)p;
    cudaGetSymbolAddress(&p, g_om);   om  = (float*)p;
    cudaGetSymbolAddress(&p, g_msg);  msg = (float*)p;
    cudaGetSymbolAddress(&p, g_cat);  cat = (float*)p;
    cudaGetSymbolAddress(&p, g_h);    h   = (float*)p;
    cudaGetSymbolAddress(&p, g_h2);   h2  = (float*)p;
    cudaGetSymbolAddress(&p, g_Mq);   Mq  = (float*)p;
    cudaGetSymbolAddress(&p, g_Mqi);  Mqi = (float*)p;
    cudaGetSymbolAddress(&p, g_Mkv);  Mkv = (float*)p;

    const int ROWS = NVB * LTOK;                 // 6144
    const int NEL  = ROWS * CC;                  // 1.57M
    const float iscale = 0.125f;                 // 1/sqrt(64)

    k_build_x<<<(NEL+255)/256, 256>>>(feats, x);
    k_prope_q<<<(ROWS+255)/256, 256>>>(vms, Ks, Mq, Mqi);
    k_prope_kv<<<(NVB*TKX+255)/256, 256>>>(vms, Ks, Mkv);

    for (int ly = 0; ly < 2; ly++) {
        const float* wq0 = Wq + (size_t)(ly*2+0)*CC*CC;
        const float* wk0 = Wk + (size_t)(ly*2+0)*CC*CC;
        const float* wv0 = Wv + (size_t)(ly*2+0)*CC*CC;
        const float* wm0 = Wm + (size_t)(ly*2+0)*CC*CC;
        const float* wq1 = Wq + (size_t)(ly*2+1)*CC*CC;
        const float* wk1 = Wk + (size_t)(ly*2+1)*CC*CC;
        const float* wv1 = Wv + (size_t)(ly*2+1)*CC*CC;
        const float* wm1 = Wm + (size_t)(ly*2+1)*CC*CC;

        // snapshot x for cross-attn kv (built from pre-self-attn x)
        k_copy<<<(NEL+255)/256, 256>>>(xpre, x, NEL);

        // ---------- self attention ----------
        k_gemm<true><<<gg(ROWS,CC,1), 256>>>(x, wq0, q, ROWS, CC, CC, 0,0,0, 1.f);
        k_gemm<true><<<gg(ROWS,CC,1), 256>>>(x, wk0, k, ROWS, CC, CC, 0,0,0, 1.f);
        k_gemm<true><<<gg(ROWS,CC,1), 256>>>(x, wv0, v, ROWS, CC, CC, 0,0,0, 1.f);
        k_apply_q  <<<(NVB*LTOK*NH*16)/256, 256>>>(q, Mqi, qp);
        k_apply_kv <<<(NVB*LTOK*NH*16)/256, 256>>>(k, Mq, kp, LTOK, 0);
        k_apply_kv <<<(NVB*LTOK*NH*16)/256, 256>>>(v, Mq, vp, LTOK, 0);
        k_gemm<true><<<gg(LTOK,LTOK,24), 256>>>(qp, kp, S, LTOK, LTOK, HD,
            (long long)LTOK*HD, (long long)LTOK*HD, (long long)LTOK*LTOK, iscale);
        k_softmax<<<24*LTOK, 256>>>(S, LTOK);
        k_gemm<false><<<gg(LTOK,HD,24), 256>>>(S, vp, O, LTOK, HD, LTOK,
            (long long)LTOK*LTOK, (long long)LTOK*HD, (long long)LTOK*HD, 1.f);
        k_apply_out<<<(NVB*LTOK*NH*16)/256, 256>>>(O, Mqi, om);
        k_gemm<true><<<gg(ROWS,CC,1), 256>>>(om, wm0, msg, ROWS, CC, CC, 0,0,0, 1.f);
        k_ln<<<ROWS, 256>>>(x, msg, n1w + (ly*2+0)*CC, n1b + (ly*2+0)*CC, 1);

        // ---------- cross attention ----------
        k_gemm<true><<<gg(ROWS,CC,1), 256>>>(x,    wq1, q, ROWS, CC, CC, 0,0,0, 1.f);
        k_gemm<true><<<gg(ROWS,CC,1), 256>>>(xpre, wk1, k, ROWS, CC, CC, 0,0,0, 1.f);
        k_gemm<true><<<gg(ROWS,CC,1), 256>>>(xpre, wv1, v, ROWS, CC, CC, 0,0,0, 1.f);
        k_apply_q  <<<(NVB*LTOK*NH*16)/256, 256>>>(q, Mqi, qp);
        k_apply_kv <<<(NVB*TKX*NH*16)/256, 256>>>(k, Mkv, kp, TKX, 1);
        k_apply_kv <<<(NVB*TKX*NH*16)/256, 256>>>(v, Mkv, vp, TKX, 1);
        k_gemm<true><<<gg(LTOK,TKX,24), 256>>>(qp, kp, S, LTOK, TKX, HD,
            (long long)LTOK*HD, (long long)TKX*HD, (long long)LTOK*TKX, iscale);
        k_softmax<<<24*LTOK, 256>>>(S, TKX);
        k_gemm<false><<<gg(LTOK,HD,24), 256>>>(S, vp, O, LTOK, HD, TKX,
            (long long)LTOK*TKX, (long long)TKX*HD, (long long)LTOK*HD, 1.f);
        k_apply_out<<<(NVB*LTOK*NH*16)/256, 256>>>(O, Mqi, om);
        k_gemm<true><<<gg(ROWS,CC,1), 256>>>(om, wm1, msg, ROWS, CC, CC, 0,0,0, 1.f);
        k_ln<<<ROWS, 256>>>(msg, msg, n1w + (ly*2+1)*CC, n1b + (ly*2+1)*CC, 0);

        // ---------- FFN ----------
        k_cat<<<(ROWS*FFNI)/256, 256>>>(x, msg, cat);
        k_gemm<true><<<gg(ROWS,FFNH,1), 256>>>(cat, W1 + (size_t)ly*FFNH*FFNI, h,
            ROWS, FFNH, FFNI, 0,0,0, 1.f);
        k_gelu<<<(ROWS*FFNH+255)/256, 256>>>(h, ROWS*FFNH);
        k_gemm<true><<<gg(ROWS,CC,1), 256>>>(h, W2 + (size_t)ly*CC*FFNH, h2,
            ROWS, CC, FFNH, 0,0,0, 1.f);
        k_ln<<<ROWS, 256>>>(x, h2, n2w + ly*CC, n2b + ly*CC, 1);
    }

    k_final<<<(NEL+255)/256, 256>>>(x, (float*)d_out);
}

// round 4
// speedup vs baseline: 1.5510x; 1.5510x over previous
#include <cuda_runtime.h>
#include <cuda_bf16.h>
#include <math.h>
#include <stdint.h>

// ---------------- problem constants ----------------
#define NVB   6
#define VV    3
#define BB    2
#define CC    256
#define LTOK  1024
#define TKX   2048
#define NH    4
#define HD    64
#define FFNI  512
#define FFNH  2048

// ---------------- device scratch ----------------
__device__ float g_x   [NVB*LTOK*CC];
__device__ float g_xpre[NVB*LTOK*CC];
__device__ float g_q   [NVB*LTOK*CC];
__device__ float g_k   [NVB*LTOK*CC];
__device__ float g_v   [NVB*LTOK*CC];
__device__ float g_qp  [NVB*NH*LTOK*HD];
__device__ float g_kp  [NVB*NH*TKX*HD];
__device__ float g_vp  [NVB*NH*TKX*HD];     // TRANSPOSED: [n][h][HD][Tk]
__device__ float g_S   [(size_t)NVB*NH*LTOK*TKX];
__device__ float g_O   [NVB*NH*LTOK*HD];
__device__ float g_om  [NVB*LTOK*CC];
__device__ float g_msg [NVB*LTOK*CC];
__device__ float g_cat [NVB*LTOK*FFNI];
__device__ float g_h   [NVB*LTOK*FFNH];
__device__ float g_h2  [NVB*LTOK*CC];
__device__ float g_Mq  [NVB*LTOK*16];
__device__ float g_Mqi [NVB*LTOK*16];
__device__ float g_Mkv [NVB*TKX*16];

// ---------------- bf16 split helpers ----------------
__device__ __forceinline__ void cvt_hl(float x, float y, uint32_t& hi, uint32_t& lo) {
    __nv_bfloat162 h = __floats2bfloat162_rn(x, y);
    float rx = x - __bfloat162float(h.x);
    float ry = y - __bfloat162float(h.y);
    __nv_bfloat162 l = __floats2bfloat162_rn(rx, ry);
    hi = *reinterpret_cast<uint32_t*>(&h);
    lo = *reinterpret_cast<uint32_t*>(&l);
}

__device__ __forceinline__ void mma_bf16(float* c, const uint32_t* a, const uint32_t* b) {
    asm volatile(
        "mma.sync.aligned.m16n8k16.row.col.f32.bf16.bf16.f32 "
        "{%0,%1,%2,%3}, {%4,%5,%6,%7}, {%8,%9}, {%0,%1,%2,%3};"
        : "+f"(c[0]), "+f"(c[1]), "+f"(c[2]), "+f"(c[3])
        : "r"(a[0]), "r"(a[1]), "r"(a[2]), "r"(a[3]), "r"(b[0]), "r"(b[1]));
}

// ---------------- tensor-core bf16x3 GEMM: C = alpha * A @ B^T ----------------
// A [M,K] rm, B [N,K] rm, C [M,N]. M%128==0, N%BN==0, K%16==0.
// hi/lo bf16 split: A*B ~= Ah*Bh + Ah*Bl + Al*Bh  (fp32 accumulate)
template<int BN>
__global__ __launch_bounds__(256)
void tc_gemm(const float* __restrict__ A, const float* __restrict__ B,
             float* __restrict__ C, int M, int N, int K,
             long long sA, long long sB, long long sC, float alpha)
{
    constexpr int S = 12;                          // u32 words per row (24 bf16, BK=16)
    constexpr int WARPS_N = (BN == 128) ? 4 : 2;
    constexpr int WM = (BN == 128) ? 64 : 32;
    constexpr int MT = WM / 16;                    // 4 or 2
    constexpr int NT2 = 4;

    extern __shared__ uint32_t sm[];
    uint32_t* as_hi = sm;                          // [2][128*S]
    uint32_t* as_lo = as_hi + 2 * 128 * S;
    uint32_t* bs_hi = as_lo + 2 * 128 * S;         // [2][BN*S]
    uint32_t* bs_lo = bs_hi + 2 * BN * S;

    A += (long long)blockIdx.z * sA;
    B += (long long)blockIdx.z * sB;
    C += (long long)blockIdx.z * sC;
    const int m0 = blockIdx.y * 128;
    const int n0 = blockIdx.x * BN;
    const int tid = threadIdx.x;
    const int wid = tid >> 5, lane = tid & 31;
    const int g = lane >> 2, tg = lane & 3;
    const int warp_m = wid / WARPS_N, warp_n = wid % WARPS_N;
    const int wm0 = warp_m * WM, wn0 = warp_n * 32;

    const int rowa = tid >> 1, ca = (tid & 1) * 8;     // A: 8 floats/thread
    const int rowb128 = tid >> 1;                       // B(BN=128): 8 floats/thread
    const int rowb64  = tid >> 2, cb64 = (tid & 3) * 4; // B(BN=64): 4 floats/thread

    float acc[MT][NT2][4];
    #pragma unroll
    for (int i = 0; i < MT; i++)
        #pragma unroll
        for (int j = 0; j < NT2; j++)
            #pragma unroll
            for (int r = 0; r < 4; r++) acc[i][j][r] = 0.f;

    const int nk = K >> 4;

    // ---- tile store helpers (as lambdas via macros) ----
    #define STORE_A(stage, v0, v1) do {                                          \
        uint32_t base = (stage) * 128 * S + rowa * S + (tid & 1) * 4;            \
        uint32_t h, l;                                                           \
        cvt_hl((v0).x, (v0).y, h, l); as_hi[base+0] = h; as_lo[base+0] = l;      \
        cvt_hl((v0).z, (v0).w, h, l); as_hi[base+1] = h; as_lo[base+1] = l;      \
        cvt_hl((v1).x, (v1).y, h, l); as_hi[base+2] = h; as_lo[base+2] = l;      \
        cvt_hl((v1).z, (v1).w, h, l); as_hi[base+3] = h; as_lo[base+3] = l;      \
    } while (0)
    #define STORE_B128(stage, v0, v1) do {                                       \
        uint32_t base = (stage) * BN * S + rowb128 * S + (tid & 1) * 4;          \
        uint32_t h, l;                                                           \
        cvt_hl((v0).x, (v0).y, h, l); bs_hi[base+0] = h; bs_lo[base+0] = l;      \
        cvt_hl((v0).z, (v0).w, h, l); bs_hi[base+1] = h; bs_lo[base+1] = l;      \
        cvt_hl((v1).x, (v1).y, h, l); bs_hi[base+2] = h; bs_lo[base+2] = l;      \
        cvt_hl((v1).z, (v1).w, h, l); bs_hi[base+3] = h; bs_lo[base+3] = l;      \
    } while (0)
    #define STORE_B64(stage, v0) do {                                            \
        uint32_t base = (stage) * BN * S + rowb64 * S + (tid & 3) * 2;           \
        uint32_t h, l;                                                           \
        cvt_hl((v0).x, (v0).y, h, l); bs_hi[base+0] = h; bs_lo[base+0] = l;      \
        cvt_hl((v0).z, (v0).w, h, l); bs_hi[base+1] = h; bs_lo[base+1] = l;      \
    } while (0)

    // prologue: tile 0 -> stage 0
    {
        const float* pa = A + (long long)(m0 + rowa) * K + ca;
        float4 v0 = *reinterpret_cast<const float4*>(pa);
        float4 v1 = *reinterpret_cast<const float4*>(pa + 4);
        STORE_A(0, v0, v1);
        if (BN == 128) {
            const float* pb = B + (long long)(n0 + rowb128) * K + ca;
            float4 w0 = *reinterpret_cast<const float4*>(pb);
            float4 w1 = *reinterpret_cast<const float4*>(pb + 4);
            STORE_B128(0, w0, w1);
        } else {
            const float* pb = B + (long long)(n0 + rowb64) * K + cb64;
            float4 w0 = *reinterpret_cast<const float4*>(pb);
            STORE_B64(0, w0);
        }
    }
    __syncthreads();

    for (int kt = 0; kt < nk; kt++) {
        const int cur = kt & 1, nxt = cur ^ 1;
        float4 pva0, pva1, pvb0, pvb1;
        if (kt + 1 < nk) {
            const float* pa = A + (long long)(m0 + rowa) * K + (kt + 1) * 16 + ca;
            pva0 = *reinterpret_cast<const float4*>(pa);
            pva1 = *reinterpret_cast<const float4*>(pa + 4);
            if (BN == 128) {
                const float* pb = B + (long long)(n0 + rowb128) * K + (kt + 1) * 16 + ca;
                pvb0 = *reinterpret_cast<const float4*>(pb);
                pvb1 = *reinterpret_cast<const float4*>(pb + 4);
            } else {
                const float* pb = B + (long long)(n0 + rowb64) * K + (kt + 1) * 16 + cb64;
                pvb0 = *reinterpret_cast<const float4*>(pb);
            }
        }

        // compute on current stage: one k=16 step, 3 mma products
        {
            uint32_t ah[MT][4], al[MT][4], bh[NT2][2], bl[NT2][2];
            #pragma unroll
            for (int mi = 0; mi < MT; mi++) {
                uint32_t off = cur * 128 * S + (wm0 + mi * 16 + g) * S + tg;
                ah[mi][0] = as_hi[off];         ah[mi][1] = as_hi[off + 8 * S];
                ah[mi][2] = as_hi[off + 4];     ah[mi][3] = as_hi[off + 8 * S + 4];
                al[mi][0] = as_lo[off];         al[mi][1] = as_lo[off + 8 * S];
                al[mi][2] = as_lo[off + 4];     al[mi][3] = as_lo[off + 8 * S + 4];
            }
            #pragma unroll
            for (int ni = 0; ni < NT2; ni++) {
                uint32_t off = cur * BN * S + (wn0 + ni * 8 + g) * S + tg;
                bh[ni][0] = bs_hi[off];  bh[ni][1] = bs_hi[off + 4];
                bl[ni][0] = bs_lo[off];  bl[ni][1] = bs_lo[off + 4];
            }
            #pragma unroll
            for (int mi = 0; mi < MT; mi++)
                #pragma unroll
                for (int ni = 0; ni < NT2; ni++) {
                    mma_bf16(acc[mi][ni], ah[mi], bh[ni]);
                    mma_bf16(acc[mi][ni], ah[mi], bl[ni]);
                    mma_bf16(acc[mi][ni], al[mi], bh[ni]);
                }
        }

        if (kt + 1 < nk) {
            STORE_A(nxt, pva0, pva1);
            if (BN == 128) STORE_B128(nxt, pvb0, pvb1);
            else           STORE_B64(nxt, pvb0);
            __syncthreads();
        }
    }

    // epilogue
    #pragma unroll
    for (int mi = 0; mi < MT; mi++) {
        #pragma unroll
        for (int ni = 0; ni < NT2; ni++) {
            long long row0 = m0 + wm0 + mi * 16 + g;
            int col = n0 + wn0 + ni * 8 + tg * 2;
            float2 v0 = make_float2(acc[mi][ni][0] * alpha, acc[mi][ni][1] * alpha);
            float2 v1 = make_float2(acc[mi][ni][2] * alpha, acc[mi][ni][3] * alpha);
            *reinterpret_cast<float2*>(&C[row0 * N + col]) = v0;
            *reinterpret_cast<float2*>(&C[(row0 + 8) * N + col]) = v1;
        }
    }
    #undef STORE_A
    #undef STORE_B128
    #undef STORE_B64
}

// ---------------- layout kernels ----------------
__global__ void k_build_x(const float* __restrict__ f, float* __restrict__ x) {
    int idx = blockIdx.x * blockDim.x + threadIdx.x;
    if (idx >= NVB*LTOK*CC) return;
    int c = idx & (CC-1);
    int l = (idx >> 8) & (LTOK-1);
    int n = idx >> 18;
    x[idx] = f[((size_t)n*CC + c)*LTOK + l];
}

__global__ void k_final(const float* __restrict__ x, float* __restrict__ o) {
    int idx = blockIdx.x * blockDim.x + threadIdx.x;
    if (idx >= NVB*LTOK*CC) return;
    int l = idx & (LTOK-1);
    int c = (idx >> 10) & (CC-1);
    int n = idx >> 18;
    o[idx] = x[((size_t)n*LTOK + l)*CC + c];
}

__global__ void k_copy(float* __restrict__ d, const float* __restrict__ s, int nelem) {
    int i = blockIdx.x * blockDim.x + threadIdx.x;
    if (i < nelem) d[i] = s[i];
}

// ---------------- PRoPE matrix build ----------------
__device__ __forceinline__ void prope_forward(const float* vm, const float* Kc,
                                              float u, float vyy, float* M) {
    float fx = Kc[0] * (1.0f/128.0f), fy = Kc[4] * (1.0f/128.0f);
    float cx = Kc[2] * (1.0f/128.0f), cy = Kc[5] * (1.0f/128.0f);
    float a = cx - u, b = cy - vyy;
    #pragma unroll
    for (int c = 0; c < 4; c++) {
        M[0*4+c] = fx*vm[0*4+c] + a*vm[2*4+c];
        M[1*4+c] = fy*vm[1*4+c] + b*vm[2*4+c];
        M[2*4+c] = vm[2*4+c];
        M[3*4+c] = vm[3*4+c];
    }
}

__global__ void k_prope_q(const float* __restrict__ vms, const float* __restrict__ Ks,
                          float* __restrict__ Mq, float* __restrict__ Mqi) {
    int idx = blockIdx.x * blockDim.x + threadIdx.x;
    if (idx >= NVB*LTOK) return;
    int n = idx >> 10, t = idx & (LTOK-1);
    int px = t & 31, py = t >> 5;
    float u  = (px + 0.5f) * (1.0f/32.0f);
    float vy = (py + 0.5f) * (1.0f/32.0f);
    const float* vm = vms + n*16;
    const float* Kc = Ks + n*9;
    float M[16];
    prope_forward(vm, Kc, u, vy, M);
    #pragma unroll
    for (int i = 0; i < 16; i++) Mq[idx*16+i] = M[i];

    float r00=vm[0],r01=vm[1],r02=vm[2],  t0=vm[3];
    float r10=vm[4],r11=vm[5],r12=vm[6],  t1=vm[7];
    float r20=vm[8],r21=vm[9],r22=vm[10], t2=vm[11];
    float det = r00*(r11*r22-r12*r21) - r01*(r10*r22-r12*r20) + r02*(r10*r21-r11*r20);
    float id = 1.0f/det;
    float Ri[9];
    Ri[0]=(r11*r22-r12*r21)*id; Ri[1]=(r02*r21-r01*r22)*id; Ri[2]=(r01*r12-r02*r11)*id;
    Ri[3]=(r12*r20-r10*r22)*id; Ri[4]=(r00*r22-r02*r20)*id; Ri[5]=(r02*r10-r00*r12)*id;
    Ri[6]=(r10*r21-r11*r20)*id; Ri[7]=(r01*r20-r00*r21)*id; Ri[8]=(r00*r11-r01*r10)*id;
    float ti0 = -(Ri[0]*t0 + Ri[1]*t1 + Ri[2]*t2);
    float ti1 = -(Ri[3]*t0 + Ri[4]*t1 + Ri[5]*t2);
    float ti2 = -(Ri[6]*t0 + Ri[7]*t1 + Ri[8]*t2);
    float fx = Kc[0]*(1.0f/128.0f), fy = Kc[4]*(1.0f/128.0f);
    float cx = Kc[2]*(1.0f/128.0f), cy = Kc[5]*(1.0f/128.0f);
    float a = cx - u, b = cy - vy;
    float ifx = 1.0f/fx, ify = 1.0f/fy;
    float Mi[16];
    float tv[3] = {ti0, ti1, ti2};
    #pragma unroll
    for (int i = 0; i < 3; i++) {
        Mi[i*4+0] = Ri[i*3+0]*ifx;
        Mi[i*4+1] = Ri[i*3+1]*ify;
        Mi[i*4+2] = -Ri[i*3+0]*a*ifx - Ri[i*3+1]*b*ify + Ri[i*3+2];
        Mi[i*4+3] = tv[i];
    }
    Mi[12]=0.f; Mi[13]=0.f; Mi[14]=0.f; Mi[15]=1.f;
    #pragma unroll
    for (int i = 0; i < 16; i++) Mqi[idx*16+i] = Mi[i];
}

__global__ void k_prope_kv(const float* __restrict__ vms, const float* __restrict__ Ks,
                           float* __restrict__ Mkv) {
    int idx = blockIdx.x * blockDim.x + threadIdx.x;
    if (idx >= NVB*TKX) return;
    int n = idx >> 11, tt = idx & (TKX-1);
    int m = tt >> 10, l = tt & (LTOK-1);
    int vvi = n >> 1, b = n & 1;
    int j = m + (m >= vvi ? 1 : 0);
    int cam = j*BB + b;
    int px = l & 31, py = l >> 5;
    float u  = (px + 0.5f)*(1.0f/32.0f);
    float vy = (py + 0.5f)*(1.0f/32.0f);
    float M[16];
    prope_forward(vms + cam*16, Ks + cam*9, u, vy, M);
    #pragma unroll
    for (int i = 0; i < 16; i++) Mkv[idx*16+i] = M[i];
}

// ---------------- per-token 4x4 projective applies ----------------
__global__ void k_apply_q(const float* __restrict__ q, const float* __restrict__ Mi,
                          float* __restrict__ qp) {
    int idx = blockIdx.x * blockDim.x + threadIdx.x;
    if (idx >= NVB*LTOK*NH*16) return;
    int g = idx & 15, h = (idx >> 4) & 3, t = (idx >> 6) & (LTOK-1), n = idx >> 16;
    const float* M = Mi + ((size_t)(n*LTOK + t))*16;
    const float* s = q + ((size_t)(n*LTOK + t))*CC + h*HD + g*4;
    float x0=s[0], x1=s[1], x2=s[2], x3=s[3];
    float* d = qp + (((size_t)(n*NH + h))*LTOK + t)*HD + g*4;
    #pragma unroll
    for (int i = 0; i < 4; i++)
        d[i] = M[0*4+i]*x0 + M[1*4+i]*x1 + M[2*4+i]*x2 + M[3*4+i]*x3;
}

__global__ void k_apply_kv(const float* __restrict__ ks, const float* __restrict__ Mats,
                           float* __restrict__ kp, int Tk, int gather) {
    int idx = blockIdx.x * blockDim.x + threadIdx.x;
    if (idx >= NVB*Tk*NH*16) return;
    int g = idx & 15, h = (idx >> 4) & 3;
    int tt = (idx >> 6) % Tk, n = (idx >> 6) / Tk;
    size_t srcRow;
    if (gather) {
        int m = tt >> 10, l = tt & (LTOK-1);
        int vvi = n >> 1, b = n & 1;
        int j = m + (m >= vvi ? 1 : 0);
        srcRow = (size_t)(j*BB + b)*LTOK + l;
    } else {
        srcRow = (size_t)n*LTOK + tt;
    }
    const float* M = Mats + ((size_t)n*Tk + tt)*16;
    const float* s = ks + srcRow*CC + h*HD + g*4;
    float x0=s[0], x1=s[1], x2=s[2], x3=s[3];
    float* d = kp + (((size_t)(n*NH + h))*Tk + tt)*HD + g*4;
    #pragma unroll
    for (int i = 0; i < 4; i++)
        d[i] = M[i*4+0]*x0 + M[i*4+1]*x1 + M[i*4+2]*x2 + M[i*4+3]*x3;
}

__global__ void k_apply_v_t(const float* __restrict__ vs, const float* __restrict__ Mats,
                            float* __restrict__ vpT, int Tk, int gather) {
    int idx = blockIdx.x * blockDim.x + threadIdx.x;
    if (idx >= NVB*NH*16*Tk) return;
    int tt = idx % Tk;
    int rest = idx / Tk;
    int g = rest & 15, h = (rest >> 4) & 3, n = rest >> 6;
    size_t srcRow;
    if (gather) {
        int m = tt >> 10, l = tt & (LTOK-1);
        int vvi = n >> 1, b = n & 1;
        int j = m + (m >= vvi ? 1 : 0);
        srcRow = (size_t)(j*BB + b)*LTOK + l;
    } else {
        srcRow = (size_t)n*LTOK + tt;
    }
    const float* M = Mats + ((size_t)n*Tk + tt)*16;
    const float* s = vs + srcRow*CC + h*HD + g*4;
    float x0=s[0], x1=s[1], x2=s[2], x3=s[3];
    float* dbase = vpT + ((size_t)(n*NH + h)*HD + g*4)*Tk + tt;
    #pragma unroll
    for (int i = 0; i < 4; i++)
        dbase[(size_t)i*Tk] = M[i*4+0]*x0 + M[i*4+1]*x1 + M[i*4+2]*x2 + M[i*4+3]*x3;
}

__global__ void k_apply_out(const float* __restrict__ O, const float* __restrict__ Mi,
                            float* __restrict__ om) {
    int idx = blockIdx.x * blockDim.x + threadIdx.x;
    if (idx >= NVB*LTOK*NH*16) return;
    int g = idx & 15, h = (idx >> 4) & 3, t = (idx >> 6) & (LTOK-1), n = idx >> 16;
    const float* M = Mi + ((size_t)(n*LTOK + t))*16;
    const float* s = O + (((size_t)(n*NH + h))*LTOK + t)*HD + g*4;
    float x0=s[0], x1=s[1], x2=s[2], x3=s[3];
    float* d = om + ((size_t)(n*LTOK + t))*CC + h*HD + g*4;
    #pragma unroll
    for (int i = 0; i < 4; i++)
        d[i] = M[i*4+0]*x0 + M[i*4+1]*x1 + M[i*4+2]*x2 + M[i*4+3]*x3;
}

// ---------------- softmax ----------------
__global__ void k_softmax(float* __restrict__ S, int Tk) {
    float* row = S + (size_t)blockIdx.x * Tk;
    int tid = threadIdx.x;
    int nv = Tk >> 8;
    float vals[8];
    float mx = -1e30f;
    for (int i = 0; i < nv; i++) { vals[i] = row[tid + (i<<8)]; mx = fmaxf(mx, vals[i]); }
    __shared__ float red[256];
    red[tid] = mx; __syncthreads();
    for (int s = 128; s > 0; s >>= 1) { if (tid < s) red[tid] = fmaxf(red[tid], red[tid+s]); __syncthreads(); }
    mx = red[0]; __syncthreads();
    float sum = 0.f;
    for (int i = 0; i < nv; i++) { vals[i] = __expf(vals[i] - mx); sum += vals[i]; }
    red[tid] = sum; __syncthreads();
    for (int s = 128; s > 0; s >>= 1) { if (tid < s) red[tid] += red[tid+s]; __syncthreads(); }
    float inv = 1.0f / red[0];
    for (int i = 0; i < nv; i++) row[tid + (i<<8)] = vals[i] * inv;
}

// ---------------- layernorm ----------------
__global__ void k_ln(float* __restrict__ dst, const float* __restrict__ src,
                     const float* __restrict__ w, const float* __restrict__ b, int add) {
    __shared__ float red[256];
    int row = blockIdx.x, tid = threadIdx.x;
    float v = src[(size_t)row*CC + tid];
    red[tid] = v; __syncthreads();
    for (int s = 128; s > 0; s >>= 1) { if (tid < s) red[tid] += red[tid+s]; __syncthreads(); }
    float mu = red[0] * (1.0f/CC); __syncthreads();
    float d = v - mu;
    red[tid] = d * d; __syncthreads();
    for (int s = 128; s > 0; s >>= 1) { if (tid < s) red[tid] += red[tid+s]; __syncthreads(); }
    float var = red[0] * (1.0f/CC);
    float o = d * rsqrtf(var + 1e-5f) * w[tid] + b[tid];
    if (add) dst[(size_t)row*CC + tid] += o;
    else     dst[(size_t)row*CC + tid] = o;
}

// ---------------- misc elementwise ----------------
__global__ void k_cat(const float* __restrict__ x, const float* __restrict__ msg,
                      float* __restrict__ cat) {
    int idx = blockIdx.x * blockDim.x + threadIdx.x;
    if (idx >= NVB*LTOK*FFNI) return;
    int c = idx & 511, row = idx >> 9;
    cat[idx] = (c < CC) ? x[(size_t)row*CC + c] : msg[(size_t)row*CC + c - CC];
}

__global__ void k_gelu(float* __restrict__ h, int nelem) {
    int i = blockIdx.x * blockDim.x + threadIdx.x;
    if (i < nelem) {
        float v = h[i];
        h[i] = 0.5f * v * (1.0f + erff(v * 0.70710678118654752f));
    }
}

// ---------------- host driver ----------------
static const int SMEM128 = (2*128*12 + 2*128*12 + 2*128*12 + 2*128*12) * 4;  // 49152
static const int SMEM64  = (2*128*12 + 2*128*12 + 2*64*12 + 2*64*12) * 4;    // 36864

static void tcg(const float* A, const float* B, float* C, int M, int N, int K,
                long long sA, long long sB, long long sC, float alpha, int batch) {
    if (N % 128 == 0) {
        dim3 g(N/128, M/128, batch);
        tc_gemm<128><<<g, 256, SMEM128>>>(A, B, C, M, N, K, sA, sB, sC, alpha);
    } else {
        dim3 g(N/64, M/128, batch);
        tc_gemm<64><<<g, 256, SMEM64>>>(A, B, C, M, N, K, sA, sB, sC, alpha);
    }
}

extern "C" void kernel_launch(void* const* d_in, const int* in_sizes, int n_in,
                              void* d_out, int out_size) {
    const float* feats = (const float*)d_in[0];
    const float* vms   = (const float*)d_in[1];
    const float* Ks    = (const float*)d_in[2];
    const float* Wq    = (const float*)d_in[3];
    const float* Wk    = (const float*)d_in[4];
    const float* Wv    = (const float*)d_in[5];
    const float* Wm    = (const float*)d_in[6];
    const float* n1w   = (const float*)d_in[7];
    const float* n1b   = (const float*)d_in[8];
    const float* W1    = (const float*)d_in[9];
    const float* W2    = (const float*)d_in[10];
    const float* n2w   = (const float*)d_in[11];
    const float* n2b   = (const float*)d_in[12];

    void* p;
    float *x,*xpre,*q,*k,*v,*qp,*kp,*vp,*S,*O,*om,*msg,*cat,*h,*h2,*Mq,*Mqi,*Mkv;
    cudaGetSymbolAddress(&p, g_x);    x   = (float*)p;
    cudaGetSymbolAddress(&p, g_xpre); xpre= (float*)p;
    cudaGetSymbolAddress(&p, g_q);    q   = (float*)p;
    cudaGetSymbolAddress(&p, g_k);    k   = (float*)p;
    cudaGetSymbolAddress(&p, g_v);    v   = (float*)p;
    cudaGetSymbolAddress(&p, g_qp);   qp  = (float*)p;
    cudaGetSymbolAddress(&p, g_kp);   kp  = (float*)p;
    cudaGetSymbolAddress(&p, g_vp);   vp  = (float*)p;
    cudaGetSymbolAddress(&p, g_S);    S   = (float*)p;
    cudaGetSymbolAddress(&p, g_O);    O   = (float*)p;
    cudaGetSymbolAddress(&p, g_om);   om  = (float*)p;
    cudaGetSymbolAddress(&p, g_msg);  msg = (float*)p;
    cudaGetSymbolAddress(&p, g_cat);  cat = (float*)p;
    cudaGetSymbolAddress(&p, g_h);    h   = (float*)p;
    cudaGetSymbolAddress(&p, g_h2);   h2  = (float*)p;
    cudaGetSymbolAddress(&p, g_Mq);   Mq  = (float*)p;
    cudaGetSymbolAddress(&p, g_Mqi);  Mqi = (float*)p;
    cudaGetSymbolAddress(&p, g_Mkv);  Mkv = (float*)p;

    const int ROWS = NVB * LTOK;
    const int NEL  = ROWS * CC;
    const float iscale = 0.125f;

    k_build_x<<<(NEL+255)/256, 256>>>(feats, x);
    k_prope_q<<<(ROWS+255)/256, 256>>>(vms, Ks, Mq, Mqi);
    k_prope_kv<<<(NVB*TKX+255)/256, 256>>>(vms, Ks, Mkv);

    for (int ly = 0; ly < 2; ly++) {
        const float* wq0 = Wq + (size_t)(ly*2+0)*CC*CC;
        const float* wk0 = Wk + (size_t)(ly*2+0)*CC*CC;
        const float* wv0 = Wv + (size_t)(ly*2+0)*CC*CC;
        const float* wm0 = Wm + (size_t)(ly*2+0)*CC*CC;
        const float* wq1 = Wq + (size_t)(ly*2+1)*CC*CC;
        const float* wk1 = Wk + (size_t)(ly*2+1)*CC*CC;
        const float* wv1 = Wv + (size_t)(ly*2+1)*CC*CC;
        const float* wm1 = Wm + (size_t)(ly*2+1)*CC*CC;

        k_copy<<<(NEL+255)/256, 256>>>(xpre, x, NEL);

        // ---------- self attention ----------
        tcg(x, wq0, q, ROWS, CC, CC, 0,0,0, 1.f, 1);
        tcg(x, wk0, k, ROWS, CC, CC, 0,0,0, 1.f, 1);
        tcg(x, wv0, v, ROWS, CC, CC, 0,0,0, 1.f, 1);
        k_apply_q  <<<(NVB*LTOK*NH*16)/256, 256>>>(q, Mqi, qp);
        k_apply_kv <<<(NVB*LTOK*NH*16)/256, 256>>>(k, Mq, kp, LTOK, 0);
        k_apply_v_t<<<(NVB*LTOK*NH*16)/256, 256>>>(v, Mq, vp, LTOK, 0);
        tcg(qp, kp, S, LTOK, LTOK, HD,
            (long long)LTOK*HD, (long long)LTOK*HD, (long long)LTOK*LTOK, iscale, 24);
        k_softmax<<<24*LTOK, 256>>>(S, LTOK);
        tcg(S, vp, O, LTOK, HD, LTOK,
            (long long)LTOK*LTOK, (long long)HD*LTOK, (long long)LTOK*HD, 1.f, 24);
        k_apply_out<<<(NVB*LTOK*NH*16)/256, 256>>>(O, Mqi, om);
        tcg(om, wm0, msg, ROWS, CC, CC, 0,0,0, 1.f, 1);
        k_ln<<<ROWS, 256>>>(x, msg, n1w + (ly*2+0)*CC, n1b + (ly*2+0)*CC, 1);

        // ---------- cross attention ----------
        tcg(x,    wq1, q, ROWS, CC, CC, 0,0,0, 1.f, 1);
        tcg(xpre, wk1, k, ROWS, CC, CC, 0,0,0, 1.f, 1);
        tcg(xpre, wv1, v, ROWS, CC, CC, 0,0,0, 1.f, 1);
        k_apply_q  <<<(NVB*LTOK*NH*16)/256, 256>>>(q, Mqi, qp);
        k_apply_kv <<<(NVB*TKX*NH*16)/256, 256>>>(k, Mkv, kp, TKX, 1);
        k_apply_v_t<<<(NVB*TKX*NH*16)/256, 256>>>(v, Mkv, vp, TKX, 1);
        tcg(qp, kp, S, LTOK, TKX, HD,
            (long long)LTOK*HD, (long long)TKX*HD, (long long)LTOK*TKX, iscale, 24);
        k_softmax<<<24*LTOK, 256>>>(S, TKX);
        tcg(S, vp, O, LTOK, HD, TKX,
            (long long)LTOK*TKX, (long long)HD*TKX, (long long)LTOK*HD, 1.f, 24);
        k_apply_out<<<(NVB*LTOK*NH*16)/256, 256>>>(O, Mqi, om);
        tcg(om, wm1, msg, ROWS, CC, CC, 0,0,0, 1.f, 1);
        k_ln<<<ROWS, 256>>>(msg, msg, n1w + (ly*2+1)*CC, n1b + (ly*2+1)*CC, 0);

        // ---------- FFN ----------
        k_cat<<<(ROWS*FFNI)/256, 256>>>(x, msg, cat);
        tcg(cat, W1 + (size_t)ly*FFNH*FFNI, h, ROWS, FFNH, FFNI, 0,0,0, 1.f, 1);
        k_gelu<<<(ROWS*FFNH+255)/256, 256>>>(h, ROWS*FFNH);
        tcg(h, W2 + (size_t)ly*CC*FFNH, h2, ROWS, CC, FFNH, 0,0,0, 1.f, 1);
        k_ln<<<ROWS, 256>>>(x, h2, n2w + ly*CC, n2b + ly*CC, 1);
    }

    k_final<<<(NEL+255)/256, 256>>>(x, (float*)d_out);
}

// round 6
// speedup vs baseline: 1.8129x; 1.1689x over previous
#include <cuda_runtime.h>
#include <cuda_bf16.h>
#include <math.h>
#include <stdint.h>

// ---------------- problem constants ----------------
#define NVB   6
#define VV    3
#define BB    2
#define CC    256
#define LTOK  1024
#define TKX   2048
#define NH    4
#define HD    64
#define FFNI  512
#define FFNH  2048

// ---------------- device scratch ----------------
__device__ float g_x   [NVB*LTOK*CC];
__device__ float g_xpre[NVB*LTOK*CC];
__device__ float g_q   [NVB*LTOK*CC];
__device__ float g_k   [NVB*LTOK*CC];
__device__ float g_v   [NVB*LTOK*CC];
__device__ float g_qp  [NVB*NH*LTOK*HD];
__device__ float g_kp  [NVB*NH*TKX*HD];
__device__ float g_vp  [NVB*NH*TKX*HD];     // TRANSPOSED: [n][h][HD][Tk]
__device__ float g_O   [NVB*NH*LTOK*HD];
__device__ float g_om  [NVB*LTOK*CC];
__device__ float g_msg [NVB*LTOK*CC];
__device__ float g_cat [NVB*LTOK*FFNI];
__device__ float g_h   [NVB*LTOK*FFNH];
__device__ float g_h2  [NVB*LTOK*CC];
__device__ float g_Mq  [NVB*LTOK*16];
__device__ float g_Mqi [NVB*LTOK*16];
__device__ float g_Mkv [NVB*TKX*16];

// ---------------- bf16 split helpers ----------------
__device__ __forceinline__ void cvt_hl(float x, float y, uint32_t& hi, uint32_t& lo) {
    __nv_bfloat162 h = __floats2bfloat162_rn(x, y);
    float rx = x - __bfloat162float(h.x);
    float ry = y - __bfloat162float(h.y);
    __nv_bfloat162 l = __floats2bfloat162_rn(rx, ry);
    hi = *reinterpret_cast<uint32_t*>(&h);
    lo = *reinterpret_cast<uint32_t*>(&l);
}

__device__ __forceinline__ void mma_bf16(float* c, const uint32_t* a, const uint32_t* b) {
    asm volatile(
        "mma.sync.aligned.m16n8k16.row.col.f32.bf16.bf16.f32 "
        "{%0,%1,%2,%3}, {%4,%5,%6,%7}, {%8,%9}, {%0,%1,%2,%3};"
        : "+f"(c[0]), "+f"(c[1]), "+f"(c[2]), "+f"(c[3])
        : "r"(a[0]), "r"(a[1]), "r"(a[2]), "r"(a[3]), "r"(b[0]), "r"(b[1]));
}

// ---------------- tensor-core bf16x3 GEMM: C = act(alpha * A @ B^T) ----------------
template<int BN, int ACT>
__global__ __launch_bounds__(256)
void tc_gemm(const float* __restrict__ A, const float* __restrict__ B,
             float* __restrict__ C, int M, int N, int K,
             long long sA, long long sB, long long sC, float alpha)
{
    constexpr int S = 12;
    constexpr int WARPS_N = (BN == 128) ? 4 : 2;
    constexpr int WM = (BN == 128) ? 64 : 32;
    constexpr int MT = WM / 16;
    constexpr int NT2 = 4;

    extern __shared__ uint32_t sm[];
    uint32_t* as_hi = sm;
    uint32_t* as_lo = as_hi + 2 * 128 * S;
    uint32_t* bs_hi = as_lo + 2 * 128 * S;
    uint32_t* bs_lo = bs_hi + 2 * BN * S;

    A += (long long)blockIdx.z * sA;
    B += (long long)blockIdx.z * sB;
    C += (long long)blockIdx.z * sC;
    const int m0 = blockIdx.y * 128;
    const int n0 = blockIdx.x * BN;
    const int tid = threadIdx.x;
    const int wid = tid >> 5, lane = tid & 31;
    const int g = lane >> 2, tg = lane & 3;
    const int warp_m = wid / WARPS_N, warp_n = wid % WARPS_N;
    const int wm0 = warp_m * WM, wn0 = warp_n * 32;

    const int rowa = tid >> 1, ca = (tid & 1) * 8;
    const int rowb128 = tid >> 1;
    const int rowb64  = tid >> 2, cb64 = (tid & 3) * 4;

    float acc[MT][NT2][4];
    #pragma unroll
    for (int i = 0; i < MT; i++)
        #pragma unroll
        for (int j = 0; j < NT2; j++)
            #pragma unroll
            for (int r = 0; r < 4; r++) acc[i][j][r] = 0.f;

    const int nk = K >> 4;

    #define STORE_A(stage, v0, v1) do {                                          \
        uint32_t base = (stage) * 128 * S + rowa * S + (tid & 1) * 4;            \
        uint32_t h, l;                                                           \
        cvt_hl((v0).x, (v0).y, h, l); as_hi[base+0] = h; as_lo[base+0] = l;      \
        cvt_hl((v0).z, (v0).w, h, l); as_hi[base+1] = h; as_lo[base+1] = l;      \
        cvt_hl((v1).x, (v1).y, h, l); as_hi[base+2] = h; as_lo[base+2] = l;      \
        cvt_hl((v1).z, (v1).w, h, l); as_hi[base+3] = h; as_lo[base+3] = l;      \
    } while (0)
    #define STORE_B128(stage, v0, v1) do {                                       \
        uint32_t base = (stage) * BN * S + rowb128 * S + (tid & 1) * 4;          \
        uint32_t h, l;                                                           \
        cvt_hl((v0).x, (v0).y, h, l); bs_hi[base+0] = h; bs_lo[base+0] = l;      \
        cvt_hl((v0).z, (v0).w, h, l); bs_hi[base+1] = h; bs_lo[base+1] = l;      \
        cvt_hl((v1).x, (v1).y, h, l); bs_hi[base+2] = h; bs_lo[base+2] = l;      \
        cvt_hl((v1).z, (v1).w, h, l); bs_hi[base+3] = h; bs_lo[base+3] = l;      \
    } while (0)
    #define STORE_B64(stage, v0) do {                                            \
        uint32_t base = (stage) * BN * S + rowb64 * S + (tid & 3) * 2;           \
        uint32_t h, l;                                                           \
        cvt_hl((v0).x, (v0).y, h, l); bs_hi[base+0] = h; bs_lo[base+0] = l;      \
        cvt_hl((v0).z, (v0).w, h, l); bs_hi[base+1] = h; bs_lo[base+1] = l;      \
    } while (0)

    {
        const float* pa = A + (long long)(m0 + rowa) * K + ca;
        float4 v0 = *reinterpret_cast<const float4*>(pa);
        float4 v1 = *reinterpret_cast<const float4*>(pa + 4);
        STORE_A(0, v0, v1);
        if (BN == 128) {
            const float* pb = B + (long long)(n0 + rowb128) * K + ca;
            float4 w0 = *reinterpret_cast<const float4*>(pb);
            float4 w1 = *reinterpret_cast<const float4*>(pb + 4);
            STORE_B128(0, w0, w1);
        } else {
            const float* pb = B + (long long)(n0 + rowb64) * K + cb64;
            float4 w0 = *reinterpret_cast<const float4*>(pb);
            STORE_B64(0, w0);
        }
    }
    __syncthreads();

    for (int kt = 0; kt < nk; kt++) {
        const int cur = kt & 1, nxt = cur ^ 1;
        float4 pva0, pva1, pvb0, pvb1;
        if (kt + 1 < nk) {
            const float* pa = A + (long long)(m0 + rowa) * K + (kt + 1) * 16 + ca;
            pva0 = *reinterpret_cast<const float4*>(pa);
            pva1 = *reinterpret_cast<const float4*>(pa + 4);
            if (BN == 128) {
                const float* pb = B + (long long)(n0 + rowb128) * K + (kt + 1) * 16 + ca;
                pvb0 = *reinterpret_cast<const float4*>(pb);
                pvb1 = *reinterpret_cast<const float4*>(pb + 4);
            } else {
                const float* pb = B + (long long)(n0 + rowb64) * K + (kt + 1) * 16 + cb64;
                pvb0 = *reinterpret_cast<const float4*>(pb);
            }
        }
        {
            uint32_t ah[MT][4], al[MT][4], bh[NT2][2], bl[NT2][2];
            #pragma unroll
            for (int mi = 0; mi < MT; mi++) {
                uint32_t off = cur * 128 * S + (wm0 + mi * 16 + g) * S + tg;
                ah[mi][0] = as_hi[off];         ah[mi][1] = as_hi[off + 8 * S];
                ah[mi][2] = as_hi[off + 4];     ah[mi][3] = as_hi[off + 8 * S + 4];
                al[mi][0] = as_lo[off];         al[mi][1] = as_lo[off + 8 * S];
                al[mi][2] = as_lo[off + 4];     al[mi][3] = as_lo[off + 8 * S + 4];
            }
            #pragma unroll
            for (int ni = 0; ni < NT2; ni++) {
                uint32_t off = cur * BN * S + (wn0 + ni * 8 + g) * S + tg;
                bh[ni][0] = bs_hi[off];  bh[ni][1] = bs_hi[off + 4];
                bl[ni][0] = bs_lo[off];  bl[ni][1] = bs_lo[off + 4];
            }
            #pragma unroll
            for (int mi = 0; mi < MT; mi++)
                #pragma unroll
                for (int ni = 0; ni < NT2; ni++) {
                    mma_bf16(acc[mi][ni], ah[mi], bh[ni]);
                    mma_bf16(acc[mi][ni], ah[mi], bl[ni]);
                    mma_bf16(acc[mi][ni], al[mi], bh[ni]);
                }
        }
        if (kt + 1 < nk) {
            STORE_A(nxt, pva0, pva1);
            if (BN == 128) STORE_B128(nxt, pvb0, pvb1);
            else           STORE_B64(nxt, pvb0);
            __syncthreads();
        }
    }

    #pragma unroll
    for (int mi = 0; mi < MT; mi++) {
        #pragma unroll
        for (int ni = 0; ni < NT2; ni++) {
            long long row0 = m0 + wm0 + mi * 16 + g;
            int col = n0 + wn0 + ni * 8 + tg * 2;
            float r[4];
            #pragma unroll
            for (int t = 0; t < 4; t++) {
                float v = acc[mi][ni][t] * alpha;
                if (ACT == 1) v = 0.5f * v * (1.0f + erff(v * 0.70710678118654752f));
                r[t] = v;
            }
            *reinterpret_cast<float2*>(&C[row0 * N + col]) = make_float2(r[0], r[1]);
            *reinterpret_cast<float2*>(&C[(row0 + 8) * N + col]) = make_float2(r[2], r[3]);
        }
    }
    #undef STORE_A
    #undef STORE_B128
    #undef STORE_B64
}

// ---------------- fused flash attention (bf16x3, online softmax) ----------------
// Q tile = 128 rows (8 warps x 16 rows). KV chunk = 64.
// qp [nh][LTOK][64], kp [nh][Tk][64], vpT [nh][64][Tk], O [nh][LTOK][64].
// grid: (LTOK/128, NVB*NH), 256 threads.
#define FA_SK 36
__global__ __launch_bounds__(256)
void k_flash(const float* __restrict__ qp, const float* __restrict__ kp,
             const float* __restrict__ vpT, float* __restrict__ Og, int Tk)
{
    __shared__ uint32_t khw[64*FA_SK], klw[64*FA_SK];
    __shared__ uint32_t vhw[64*FA_SK], vlw[64*FA_SK];

    const int nh = blockIdx.y;
    const int q0 = blockIdx.x * 128;
    const int tid = threadIdx.x, wid = tid >> 5, lane = tid & 31;
    const int g = lane >> 2, tg = lane & 3;

    const float* Qb = qp + ((size_t)nh * LTOK + q0) * HD;
    const float* Kb = kp + (size_t)nh * Tk * HD;
    const float* Vb = vpT + (size_t)nh * HD * Tk;

    const int row0 = wid * 16 + g;        // local row within 128 (8 warps x 16)
    // Q fragments, scaled by 1/8 (exact power of 2)
    uint32_t qh[4][4], ql[4][4];
    #pragma unroll
    for (int kk = 0; kk < 4; kk++) {
        int col = kk * 16 + tg * 2;
        float2 q00 = *reinterpret_cast<const float2*>(&Qb[(size_t)row0 * HD + col]);
        float2 q01 = *reinterpret_cast<const float2*>(&Qb[(size_t)row0 * HD + col + 8]);
        float2 q10 = *reinterpret_cast<const float2*>(&Qb[(size_t)(row0 + 8) * HD + col]);
        float2 q11 = *reinterpret_cast<const float2*>(&Qb[(size_t)(row0 + 8) * HD + col + 8]);
        cvt_hl(q00.x * 0.125f, q00.y * 0.125f, qh[kk][0], ql[kk][0]);
        cvt_hl(q10.x * 0.125f, q10.y * 0.125f, qh[kk][1], ql[kk][1]);
        cvt_hl(q01.x * 0.125f, q01.y * 0.125f, qh[kk][2], ql[kk][2]);
        cvt_hl(q11.x * 0.125f, q11.y * 0.125f, qh[kk][3], ql[kk][3]);
    }

    float m0 = -1e30f, m1 = -1e30f, l0 = 0.f, l1 = 0.f;
    float oacc[8][4];
    #pragma unroll
    for (int i = 0; i < 8; i++)
        #pragma unroll
        for (int t = 0; t < 4; t++) oacc[i][t] = 0.f;

    for (int kv0 = 0; kv0 < Tk; kv0 += 64) {
        // load K chunk [64 keypos][64 d] and V^T chunk [64 d][64 keypos]
        {
            int r = tid >> 2, c = (tid & 3) * 16;
            const float* sk = Kb + (size_t)(kv0 + r) * HD + c;
            const float* sv = Vb + (size_t)r * Tk + kv0 + c;
            #pragma unroll
            for (int j = 0; j < 4; j++) {
                float4 kv = *reinterpret_cast<const float4*>(sk + j * 4);
                float4 vv = *reinterpret_cast<const float4*>(sv + j * 4);
                int w = r * FA_SK + (c >> 1) + j * 2;
                uint32_t h, l;
                cvt_hl(kv.x, kv.y, h, l); khw[w] = h;   klw[w] = l;
                cvt_hl(kv.z, kv.w, h, l); khw[w+1] = h; klw[w+1] = l;
                cvt_hl(vv.x, vv.y, h, l); vhw[w] = h;   vlw[w] = l;
                cvt_hl(vv.z, vv.w, h, l); vhw[w+1] = h; vlw[w+1] = l;
            }
        }
        __syncthreads();

        // S = (Q/8) K^T  — 16x64 per warp, 8 n-tiles
        float sacc[8][4];
        #pragma unroll
        for (int i = 0; i < 8; i++)
            #pragma unroll
            for (int t = 0; t < 4; t++) sacc[i][t] = 0.f;
        #pragma unroll
        for (int kk = 0; kk < 4; kk++) {
            #pragma unroll
            for (int ni = 0; ni < 8; ni++) {
                uint32_t bh[2], bl[2];
                int off = (ni * 8 + g) * FA_SK + kk * 8 + tg;
                bh[0] = khw[off]; bh[1] = khw[off + 4];
                bl[0] = klw[off]; bl[1] = klw[off + 4];
                mma_bf16(sacc[ni], qh[kk], bh);
                mma_bf16(sacc[ni], qh[kk], bl);
                mma_bf16(sacc[ni], ql[kk], bh);
            }
        }

        // online softmax update (rows row0 and row0+8)
        float mx0 = -1e30f, mx1 = -1e30f;
        #pragma unroll
        for (int ni = 0; ni < 8; ni++) {
            mx0 = fmaxf(mx0, fmaxf(sacc[ni][0], sacc[ni][1]));
            mx1 = fmaxf(mx1, fmaxf(sacc[ni][2], sacc[ni][3]));
        }
        mx0 = fmaxf(mx0, __shfl_xor_sync(0xffffffff, mx0, 1));
        mx0 = fmaxf(mx0, __shfl_xor_sync(0xffffffff, mx0, 2));
        mx1 = fmaxf(mx1, __shfl_xor_sync(0xffffffff, mx1, 1));
        mx1 = fmaxf(mx1, __shfl_xor_sync(0xffffffff, mx1, 2));
        float nm0 = fmaxf(m0, mx0), nm1 = fmaxf(m1, mx1);
        float al0 = __expf(m0 - nm0), al1 = __expf(m1 - nm1);
        float rs0 = 0.f, rs1 = 0.f;
        #pragma unroll
        for (int ni = 0; ni < 8; ni++) {
            sacc[ni][0] = __expf(sacc[ni][0] - nm0);
            sacc[ni][1] = __expf(sacc[ni][1] - nm0);
            sacc[ni][2] = __expf(sacc[ni][2] - nm1);
            sacc[ni][3] = __expf(sacc[ni][3] - nm1);
            rs0 += sacc[ni][0] + sacc[ni][1];
            rs1 += sacc[ni][2] + sacc[ni][3];
        }
        rs0 += __shfl_xor_sync(0xffffffff, rs0, 1);
        rs0 += __shfl_xor_sync(0xffffffff, rs0, 2);
        rs1 += __shfl_xor_sync(0xffffffff, rs1, 1);
        rs1 += __shfl_xor_sync(0xffffffff, rs1, 2);
        l0 = l0 * al0 + rs0;  l1 = l1 * al1 + rs1;
        m0 = nm0;  m1 = nm1;
        #pragma unroll
        for (int nd = 0; nd < 8; nd++) {
            oacc[nd][0] *= al0; oacc[nd][1] *= al0;
            oacc[nd][2] *= al1; oacc[nd][3] *= al1;
        }

        // O += P V  (P repacked C->A fragments, hi/lo split)
        #pragma unroll
        for (int kk = 0; kk < 4; kk++) {
            uint32_t ph[4], pl[4];
            cvt_hl(sacc[2*kk][0],   sacc[2*kk][1],   ph[0], pl[0]);
            cvt_hl(sacc[2*kk][2],   sacc[2*kk][3],   ph[1], pl[1]);
            cvt_hl(sacc[2*kk+1][0], sacc[2*kk+1][1], ph[2], pl[2]);
            cvt_hl(sacc[2*kk+1][2], sacc[2*kk+1][3], ph[3], pl[3]);
            #pragma unroll
            for (int nd = 0; nd < 8; nd++) {
                uint32_t vh[2], vl[2];
                int off = (nd * 8 + g) * FA_SK + kk * 8 + tg;
                vh[0] = vhw[off]; vh[1] = vhw[off + 4];
                vl[0] = vlw[off]; vl[1] = vlw[off + 4];
                mma_bf16(oacc[nd], ph, vh);
                mma_bf16(oacc[nd], ph, vl);
                mma_bf16(oacc[nd], pl, vh);
            }
        }
        __syncthreads();
    }

    float il0 = 1.0f / l0, il1 = 1.0f / l1;
    float* Ob = Og + ((size_t)nh * LTOK + q0) * HD;
    #pragma unroll
    for (int nd = 0; nd < 8; nd++) {
        int col = nd * 8 + tg * 2;
        *reinterpret_cast<float2*>(&Ob[(size_t)row0 * HD + col]) =
            make_float2(oacc[nd][0] * il0, oacc[nd][1] * il0);
        *reinterpret_cast<float2*>(&Ob[(size_t)(row0 + 8) * HD + col]) =
            make_float2(oacc[nd][2] * il1, oacc[nd][3] * il1);
    }
}

// ---------------- layout kernels ----------------
__global__ void k_build_x(const float* __restrict__ f, float* __restrict__ x) {
    int idx = blockIdx.x * blockDim.x + threadIdx.x;
    if (idx >= NVB*LTOK*CC) return;
    int c = idx & (CC-1);
    int l = (idx >> 8) & (LTOK-1);
    int n = idx >> 18;
    x[idx] = f[((size_t)n*CC + c)*LTOK + l];
}

__global__ void k_final(const float* __restrict__ x, float* __restrict__ o) {
    int idx = blockIdx.x * blockDim.x + threadIdx.x;
    if (idx >= NVB*LTOK*CC) return;
    int l = idx & (LTOK-1);
    int c = (idx >> 10) & (CC-1);
    int n = idx >> 18;
    o[idx] = x[((size_t)n*LTOK + l)*CC + c];
}

__global__ void k_copy(float* __restrict__ d, const float* __restrict__ s, int nelem) {
    int i = blockIdx.x * blockDim.x + threadIdx.x;
    if (i < nelem) d[i] = s[i];
}

// ---------------- PRoPE matrix build ----------------
__device__ __forceinline__ void prope_forward(const float* vm, const float* Kc,
                                              float u, float vyy, float* M) {
    float fx = Kc[0] * (1.0f/128.0f), fy = Kc[4] * (1.0f/128.0f);
    float cx = Kc[2] * (1.0f/128.0f), cy = Kc[5] * (1.0f/128.0f);
    float a = cx - u, b = cy - vyy;
    #pragma unroll
    for (int c = 0; c < 4; c++) {
        M[0*4+c] = fx*vm[0*4+c] + a*vm[2*4+c];
        M[1*4+c] = fy*vm[1*4+c] + b*vm[2*4+c];
        M[2*4+c] = vm[2*4+c];
        M[3*4+c] = vm[3*4+c];
    }
}

__global__ void k_prope_q(const float* __restrict__ vms, const float* __restrict__ Ks,
                          float* __restrict__ Mq, float* __restrict__ Mqi) {
    int idx = blockIdx.x * blockDim.x + threadIdx.x;
    if (idx >= NVB*LTOK) return;
    int n = idx >> 10, t = idx & (LTOK-1);
    int px = t & 31, py = t >> 5;
    float u  = (px + 0.5f) * (1.0f/32.0f);
    float vy = (py + 0.5f) * (1.0f/32.0f);
    const float* vm = vms + n*16;
    const float* Kc = Ks + n*9;
    float M[16];
    prope_forward(vm, Kc, u, vy, M);
    #pragma unroll
    for (int i = 0; i < 16; i++) Mq[idx*16+i] = M[i];

    float r00=vm[0],r01=vm[1],r02=vm[2],  t0=vm[3];
    float r10=vm[4],r11=vm[5],r12=vm[6],  t1=vm[7];
    float r20=vm[8],r21=vm[9],r22=vm[10], t2=vm[11];
    float det = r00*(r11*r22-r12*r21) - r01*(r10*r22-r12*r20) + r02*(r10*r21-r11*r20);
    float id = 1.0f/det;
    float Ri[9];
    Ri[0]=(r11*r22-r12*r21)*id; Ri[1]=(r02*r21-r01*r22)*id; Ri[2]=(r01*r12-r02*r11)*id;
    Ri[3]=(r12*r20-r10*r22)*id; Ri[4]=(r00*r22-r02*r20)*id; Ri[5]=(r02*r10-r00*r12)*id;
    Ri[6]=(r10*r21-r11*r20)*id; Ri[7]=(r01*r20-r00*r21)*id; Ri[8]=(r00*r11-r01*r10)*id;
    float ti0 = -(Ri[0]*t0 + Ri[1]*t1 + Ri[2]*t2);
    float ti1 = -(Ri[3]*t0 + Ri[4]*t1 + Ri[5]*t2);
    float ti2 = -(Ri[6]*t0 + Ri[7]*t1 + Ri[8]*t2);
    float fx = Kc[0]*(1.0f/128.0f), fy = Kc[4]*(1.0f/128.0f);
    float cx = Kc[2]*(1.0f/128.0f), cy = Kc[5]*(1.0f/128.0f);
    float a = cx - u, b = cy - vy;
    float ifx = 1.0f/fx, ify = 1.0f/fy;
    float Mi[16];
    float tv[3] = {ti0, ti1, ti2};
    #pragma unroll
    for (int i = 0; i < 3; i++) {
        Mi[i*4+0] = Ri[i*3+0]*ifx;
        Mi[i*4+1] = Ri[i*3+1]*ify;
        Mi[i*4+2] = -Ri[i*3+0]*a*ifx - Ri[i*3+1]*b*ify + Ri[i*3+2];
        Mi[i*4+3] = tv[i];
    }
    Mi[12]=0.f; Mi[13]=0.f; Mi[14]=0.f; Mi[15]=1.f;
    #pragma unroll
    for (int i = 0; i < 16; i++) Mqi[idx*16+i] = Mi[i];
}

__global__ void k_prope_kv(const float* __restrict__ vms, const float* __restrict__ Ks,
                           float* __restrict__ Mkv) {
    int idx = blockIdx.x * blockDim.x + threadIdx.x;
    if (idx >= NVB*TKX) return;
    int n = idx >> 11, tt = idx & (TKX-1);
    int m = tt >> 10, l = tt & (LTOK-1);
    int vvi = n >> 1, b = n & 1;
    int j = m + (m >= vvi ? 1 : 0);
    int cam = j*BB + b;
    int px = l & 31, py = l >> 5;
    float u  = (px + 0.5f)*(1.0f/32.0f);
    float vy = (py + 0.5f)*(1.0f/32.0f);
    float M[16];
    prope_forward(vms + cam*16, Ks + cam*9, u, vy, M);
    #pragma unroll
    for (int i = 0; i < 16; i++) Mkv[idx*16+i] = M[i];
}

// ---------------- per-token 4x4 projective applies ----------------
__global__ void k_apply_q(const float* __restrict__ q, const float* __restrict__ Mi,
                          float* __restrict__ qp) {
    int idx = blockIdx.x * blockDim.x + threadIdx.x;
    if (idx >= NVB*LTOK*NH*16) return;
    int g = idx & 15, h = (idx >> 4) & 3, t = (idx >> 6) & (LTOK-1), n = idx >> 16;
    const float* M = Mi + ((size_t)(n*LTOK + t))*16;
    const float* s = q + ((size_t)(n*LTOK + t))*CC + h*HD + g*4;
    float x0=s[0], x1=s[1], x2=s[2], x3=s[3];
    float* d = qp + (((size_t)(n*NH + h))*LTOK + t)*HD + g*4;
    #pragma unroll
    for (int i = 0; i < 4; i++)
        d[i] = M[0*4+i]*x0 + M[1*4+i]*x1 + M[2*4+i]*x2 + M[3*4+i]*x3;
}

__global__ void k_apply_kv(const float* __restrict__ ks, const float* __restrict__ Mats,
                           float* __restrict__ kp, int Tk, int gather) {
    int idx = blockIdx.x * blockDim.x + threadIdx.x;
    if (idx >= NVB*Tk*NH*16) return;
    int g = idx & 15, h = (idx >> 4) & 3;
    int tt = (idx >> 6) % Tk, n = (idx >> 6) / Tk;
    size_t srcRow;
    if (gather) {
        int m = tt >> 10, l = tt & (LTOK-1);
        int vvi = n >> 1, b = n & 1;
        int j = m + (m >= vvi ? 1 : 0);
        srcRow = (size_t)(j*BB + b)*LTOK + l;
    } else {
        srcRow = (size_t)n*LTOK + tt;
    }
    const float* M = Mats + ((size_t)n*Tk + tt)*16;
    const float* s = ks + srcRow*CC + h*HD + g*4;
    float x0=s[0], x1=s[1], x2=s[2], x3=s[3];
    float* d = kp + (((size_t)(n*NH + h))*Tk + tt)*HD + g*4;
    #pragma unroll
    for (int i = 0; i < 4; i++)
        d[i] = M[i*4+0]*x0 + M[i*4+1]*x1 + M[i*4+2]*x2 + M[i*4+3]*x3;
}

__global__ void k_apply_v_t(const float* __restrict__ vs, const float* __restrict__ Mats,
                            float* __restrict__ vpT, int Tk, int gather) {
    int idx = blockIdx.x * blockDim.x + threadIdx.x;
    if (idx >= NVB*NH*16*Tk) return;
    int tt = idx % Tk;
    int rest = idx / Tk;
    int g = rest & 15, h = (rest >> 4) & 3, n = rest >> 6;
    size_t srcRow;
    if (gather) {
        int m = tt >> 10, l = tt & (LTOK-1);
        int vvi = n >> 1, b = n & 1;
        int j = m + (m >= vvi ? 1 : 0);
        srcRow = (size_t)(j*BB + b)*LTOK + l;
    } else {
        srcRow = (size_t)n*LTOK + tt;
    }
    const float* M = Mats + ((size_t)n*Tk + tt)*16;
    const float* s = vs + srcRow*CC + h*HD + g*4;
    float x0=s[0], x1=s[1], x2=s[2], x3=s[3];
    float* dbase = vpT + ((size_t)(n*NH + h)*HD + g*4)*Tk + tt;
    #pragma unroll
    for (int i = 0; i < 4; i++)
        dbase[(size_t)i*Tk] = M[i*4+0]*x0 + M[i*4+1]*x1 + M[i*4+2]*x2 + M[i*4+3]*x3;
}

__global__ void k_apply_out(const float* __restrict__ O, const float* __restrict__ Mi,
                            float* __restrict__ om) {
    int idx = blockIdx.x * blockDim.x + threadIdx.x;
    if (idx >= NVB*LTOK*NH*16) return;
    int g = idx & 15, h = (idx >> 4) & 3, t = (idx >> 6) & (LTOK-1), n = idx >> 16;
    const float* M = Mi + ((size_t)(n*LTOK + t))*16;
    const float* s = O + (((size_t)(n*NH + h))*LTOK + t)*HD + g*4;
    float x0=s[0], x1=s[1], x2=s[2], x3=s[3];
    float* d = om + ((size_t)(n*LTOK + t))*CC + h*HD + g*4;
    #pragma unroll
    for (int i = 0; i < 4; i++)
        d[i] = M[i*4+0]*x0 + M[i*4+1]*x1 + M[i*4+2]*x2 + M[i*4+3]*x3;
}

// ---------------- layernorm ----------------
__global__ void k_ln(float* __restrict__ dst, const float* __restrict__ src,
                     const float* __restrict__ w, const float* __restrict__ b, int add) {
    __shared__ float red[256];
    int row = blockIdx.x, tid = threadIdx.x;
    float v = src[(size_t)row*CC + tid];
    red[tid] = v; __syncthreads();
    for (int s = 128; s > 0; s >>= 1) { if (tid < s) red[tid] += red[tid+s]; __syncthreads(); }
    float mu = red[0] * (1.0f/CC); __syncthreads();
    float d = v - mu;
    red[tid] = d * d; __syncthreads();
    for (int s = 128; s > 0; s >>= 1) { if (tid < s) red[tid] += red[tid+s]; __syncthreads(); }
    float var = red[0] * (1.0f/CC);
    float o = d * rsqrtf(var + 1e-5f) * w[tid] + b[tid];
    if (add) dst[(size_t)row*CC + tid] += o;
    else     dst[(size_t)row*CC + tid] = o;
}

// ---------------- misc elementwise ----------------
__global__ void k_cat(const float* __restrict__ x, const float* __restrict__ msg,
                      float* __restrict__ cat) {
    int idx = blockIdx.x * blockDim.x + threadIdx.x;
    if (idx >= NVB*LTOK*FFNI) return;
    int c = idx & 511, row = idx >> 9;
    cat[idx] = (c < CC) ? x[(size_t)row*CC + c] : msg[(size_t)row*CC + c - CC];
}

// ---------------- host driver ----------------
static const int SMEM128 = (2*128*12 + 2*128*12 + 2*128*12 + 2*128*12) * 4;  // 49152
static const int SMEM64  = (2*128*12 + 2*128*12 + 2*64*12 + 2*64*12) * 4;    // 36864

static void tcg(const float* A, const float* B, float* C, int M, int N, int K,
                long long sA, long long sB, long long sC, float alpha, int batch,
                int act = 0) {
    if (N % 128 == 0) {
        dim3 g(N/128, M/128, batch);
        if (act) tc_gemm<128,1><<<g, 256, SMEM128>>>(A, B, C, M, N, K, sA, sB, sC, alpha);
        else     tc_gemm<128,0><<<g, 256, SMEM128>>>(A, B, C, M, N, K, sA, sB, sC, alpha);
    } else {
        dim3 g(N/64, M/128, batch);
        tc_gemm<64,0><<<g, 256, SMEM64>>>(A, B, C, M, N, K, sA, sB, sC, alpha);
    }
}

extern "C" void kernel_launch(void* const* d_in, const int* in_sizes, int n_in,
                              void* d_out, int out_size) {
    const float* feats = (const float*)d_in[0];
    const float* vms   = (const float*)d_in[1];
    const float* Ks    = (const float*)d_in[2];
    const float* Wq    = (const float*)d_in[3];
    const float* Wk    = (const float*)d_in[4];
    const float* Wv    = (const float*)d_in[5];
    const float* Wm    = (const float*)d_in[6];
    const float* n1w   = (const float*)d_in[7];
    const float* n1b   = (const float*)d_in[8];
    const float* W1    = (const float*)d_in[9];
    const float* W2    = (const float*)d_in[10];
    const float* n2w   = (const float*)d_in[11];
    const float* n2b   = (const float*)d_in[12];

    void* p;
    float *x,*xpre,*q,*k,*v,*qp,*kp,*vp,*O,*om,*msg,*cat,*h,*h2,*Mq,*Mqi,*Mkv;
    cudaGetSymbolAddress(&p, g_x);    x   = (float*)p;
    cudaGetSymbolAddress(&p, g_xpre); xpre= (float*)p;
    cudaGetSymbolAddress(&p, g_q);    q   = (float*)p;
    cudaGetSymbolAddress(&p, g_k);    k   = (float*)p;
    cudaGetSymbolAddress(&p, g_v);    v   = (float*)p;
    cudaGetSymbolAddress(&p, g_qp);   qp  = (float*)p;
    cudaGetSymbolAddress(&p, g_kp);   kp  = (float*)p;
    cudaGetSymbolAddress(&p, g_vp);   vp  = (float*)p;
    cudaGetSymbolAddress(&p, g_O);    O   = (float*)p;
    cudaGetSymbolAddress(&p, g_om);   om  = (float*)p;
    cudaGetSymbolAddress(&p, g_msg);  msg = (float*)p;
    cudaGetSymbolAddress(&p, g_cat);  cat = (float*)p;
    cudaGetSymbolAddress(&p, g_h);    h   = (float*)p;
    cudaGetSymbolAddress(&p, g_h2);   h2  = (float*)p;
    cudaGetSymbolAddress(&p, g_Mq);   Mq  = (float*)p;
    cudaGetSymbolAddress(&p, g_Mqi);  Mqi = (float*)p;
    cudaGetSymbolAddress(&p, g_Mkv);  Mkv = (float*)p;

    const int ROWS = NVB * LTOK;
    const int NEL  = ROWS * CC;

    k_build_x<<<(NEL+255)/256, 256>>>(feats, x);
    k_prope_q<<<(ROWS+255)/256, 256>>>(vms, Ks, Mq, Mqi);
    k_prope_kv<<<(NVB*TKX+255)/256, 256>>>(vms, Ks, Mkv);

    for (int ly = 0; ly < 2; ly++) {
        const float* wq0 = Wq + (size_t)(ly*2+0)*CC*CC;
        const float* wk0 = Wk + (size_t)(ly*2+0)*CC*CC;
        const float* wv0 = Wv + (size_t)(ly*2+0)*CC*CC;
        const float* wm0 = Wm + (size_t)(ly*2+0)*CC*CC;
        const float* wq1 = Wq + (size_t)(ly*2+1)*CC*CC;
        const float* wk1 = Wk + (size_t)(ly*2+1)*CC*CC;
        const float* wv1 = Wv + (size_t)(ly*2+1)*CC*CC;
        const float* wm1 = Wm + (size_t)(ly*2+1)*CC*CC;

        k_copy<<<(NEL+255)/256, 256>>>(xpre, x, NEL);

        // ---------- self attention ----------
        tcg(x, wq0, q, ROWS, CC, CC, 0,0,0, 1.f, 1);
        tcg(x, wk0, k, ROWS, CC, CC, 0,0,0, 1.f, 1);
        tcg(x, wv0, v, ROWS, CC, CC, 0,0,0, 1.f, 1);
        k_apply_q  <<<(NVB*LTOK*NH*16)/256, 256>>>(q, Mqi, qp);
        k_apply_kv <<<(NVB*LTOK*NH*16)/256, 256>>>(k, Mq, kp, LTOK, 0);
        k_apply_v_t<<<(NVB*LTOK*NH*16)/256, 256>>>(v, Mq, vp, LTOK, 0);
        k_flash<<<dim3(LTOK/128, NVB*NH), 256>>>(qp, kp, vp, O, LTOK);
        k_apply_out<<<(NVB*LTOK*NH*16)/256, 256>>>(O, Mqi, om);
        tcg(om, wm0, msg, ROWS, CC, CC, 0,0,0, 1.f, 1);
        k_ln<<<ROWS, 256>>>(x, msg, n1w + (ly*2+0)*CC, n1b + (ly*2+0)*CC, 1);

        // ---------- cross attention ----------
        tcg(x,    wq1, q, ROWS, CC, CC, 0,0,0, 1.f, 1);
        tcg(xpre, wk1, k, ROWS, CC, CC, 0,0,0, 1.f, 1);
        tcg(xpre, wv1, v, ROWS, CC, CC, 0,0,0, 1.f, 1);
        k_apply_q  <<<(NVB*LTOK*NH*16)/256, 256>>>(q, Mqi, qp);
        k_apply_kv <<<(NVB*TKX*NH*16)/256, 256>>>(k, Mkv, kp, TKX, 1);
        k_apply_v_t<<<(NVB*TKX*NH*16)/256, 256>>>(v, Mkv, vp, TKX, 1);
        k_flash<<<dim3(LTOK/128, NVB*NH), 256>>>(qp, kp, vp, O, TKX);
        k_apply_out<<<(NVB*LTOK*NH*16)/256, 256>>>(O, Mqi, om);
        tcg(om, wm1, msg, ROWS, CC, CC, 0,0,0, 1.f, 1);
        k_ln<<<ROWS, 256>>>(msg, msg, n1w + (ly*2+1)*CC, n1b + (ly*2+1)*CC, 0);

        // ---------- FFN ----------
        k_cat<<<(ROWS*FFNI)/256, 256>>>(x, msg, cat);
        tcg(cat, W1 + (size_t)ly*FFNH*FFNI, h, ROWS, FFNH, FFNI, 0,0,0, 1.f, 1, 1);
        tcg(h, W2 + (size_t)ly*CC*FFNH, h2, ROWS, CC, FFNH, 0,0,0, 1.f, 1);
        k_ln<<<ROWS, 256>>>(x, h2, n2w + ly*CC, n2b + ly*CC, 1);
    }

    k_final<<<(NEL+255)/256, 256>>>(x, (float*)d_out);
}

// round 7
// speedup vs baseline: 1.9239x; 1.0613x over previous
#include <cuda_runtime.h>
#include <cuda_bf16.h>
#include <math.h>
#include <stdint.h>

// ---------------- problem constants ----------------
#define NVB   6
#define VV    3
#define BB    2
#define CC    256
#define LTOK  1024
#define TKX   2048
#define NH    4
#define HD    64
#define FFNI  512
#define FFNH  2048

#define ROWS_ (NVB*LTOK)          // 6144
#define XW    (NVB*LTOK*CC/2)     // words in x hi/lo

// ---------------- device scratch ----------------
__device__ float g_x   [NVB*LTOK*CC];
__device__ float g_q   [NVB*LTOK*CC];
__device__ float g_k   [NVB*LTOK*CC];
__device__ float g_v   [NVB*LTOK*CC];
__device__ float g_qp  [NVB*NH*LTOK*HD];
__device__ float g_kp  [NVB*NH*TKX*HD];
__device__ float g_vp  [NVB*NH*TKX*HD];     // TRANSPOSED: [n][h][HD][Tk]
__device__ float g_O   [NVB*NH*LTOK*HD];
__device__ float g_msg [NVB*LTOK*CC];
__device__ float g_h2  [NVB*LTOK*CC];
__device__ float g_Mq  [NVB*LTOK*16];
__device__ float g_Mqi [NVB*LTOK*16];
__device__ float g_Mkv [NVB*TKX*16];

// packed bf16 hi/lo operand buffers (u32 = bf16x2, pairs along K)
__device__ uint32_t g_xh   [XW],  g_xl   [XW];
__device__ uint32_t g_xpreh[XW],  g_xprel[XW];
__device__ uint32_t g_omh  [XW],  g_oml  [XW];
__device__ uint32_t g_cath [NVB*LTOK*FFNI/2], g_catl[NVB*LTOK*FFNI/2];
__device__ uint32_t g_hh   [NVB*LTOK*FFNH/2], g_hl  [NVB*LTOK*FFNH/2];
// weights: wq|wk|wv|wm (4 x 131072 words) + w1 (1048576) + w2 (524288)
#define WQO 0
#define WKO 131072
#define WVO 262144
#define WMO 393216
#define W1O 524288
#define W2O 1572864
__device__ uint32_t g_wh[2097152], g_wl[2097152];

// ---------------- bf16 split helpers ----------------
__device__ __forceinline__ void cvt_hl(float x, float y, uint32_t& hi, uint32_t& lo) {
    __nv_bfloat162 h = __floats2bfloat162_rn(x, y);
    float rx = x - __bfloat162float(h.x);
    float ry = y - __bfloat162float(h.y);
    __nv_bfloat162 l = __floats2bfloat162_rn(rx, ry);
    hi = *reinterpret_cast<uint32_t*>(&h);
    lo = *reinterpret_cast<uint32_t*>(&l);
}

__device__ __forceinline__ void mma_bf16(float* c, const uint32_t* a, const uint32_t* b) {
    asm volatile(
        "mma.sync.aligned.m16n8k16.row.col.f32.bf16.bf16.f32 "
        "{%0,%1,%2,%3}, {%4,%5,%6,%7}, {%8,%9}, {%0,%1,%2,%3};"
        : "+f"(c[0]), "+f"(c[1]), "+f"(c[2]), "+f"(c[3])
        : "r"(a[0]), "r"(a[1]), "r"(a[2]), "r"(a[3]), "r"(b[0]), "r"(b[1]));
}

__device__ __forceinline__ void ldsm4(uint32_t* r, uint32_t addr) {
    asm volatile("ldmatrix.sync.aligned.m8n8.x4.shared.b16 {%0,%1,%2,%3}, [%4];"
        : "=r"(r[0]), "=r"(r[1]), "=r"(r[2]), "=r"(r[3]) : "r"(addr));
}

__device__ __forceinline__ uint32_t smem_u32(const void* p) {
    uint32_t a;
    asm("{ .reg .u64 t; cvta.to.shared.u64 t, %1; cvt.u32.u64 %0, t; }" : "=r"(a) : "l"(p));
    return a;
}

// ---------------- float -> bf16 hi/lo conversion kernel ----------------
__global__ void k_cvt(const float* __restrict__ src, uint32_t* __restrict__ hi,
                      uint32_t* __restrict__ lo, int nw) {
    int i = blockIdx.x * blockDim.x + threadIdx.x;
    if (i >= nw) return;
    float2 v = reinterpret_cast<const float2*>(src)[i];
    uint32_t h, l;
    cvt_hl(v.x, v.y, h, l);
    hi[i] = h; lo[i] = l;
}

// ---------------- tensor-core bf16x3 GEMM v2 (preconverted operands) ----------
// C = act(A @ B^T). A hi/lo [M, K/2 words], B hi/lo [N, K/2 words].
// OUT=0: C fp32.  OUT=1: GELU then write Oh/Ol bf16 hi/lo words.
// M%128==0, N%128==0, K%16==0.  256 threads, warp tile 64x32 (2x4 warps).
template<int OUT>
__global__ __launch_bounds__(256)
void tc_gemm2(const uint32_t* __restrict__ Ah, const uint32_t* __restrict__ Al,
              const uint32_t* __restrict__ Bh, const uint32_t* __restrict__ Bl,
              float* __restrict__ C, uint32_t* __restrict__ Oh, uint32_t* __restrict__ Ol,
              int M, int N, int K)
{
    constexpr int S = 12;               // words per row (8 data + 4 pad)
    __shared__ uint32_t ash[2][128*S], asl[2][128*S];
    __shared__ uint32_t bsh[2][128*S], bsl[2][128*S];

    const int m0 = blockIdx.y * 128;
    const int n0 = blockIdx.x * 128;
    const int tid = threadIdx.x;
    const int wid = tid >> 5, lane = tid & 31;
    const int g = lane >> 2, tg = lane & 3;
    const int warp_m = wid >> 2, warp_n = wid & 3;     // 2 x 4
    const int wm0 = warp_m * 64, wn0 = warp_n * 32;
    const int K2 = K >> 1;

    // global load mapping: thread -> (row, half)
    const int rowa = tid >> 1, hw = (tid & 1) * 4;     // word offset within 8-word row

    // ldmatrix lane offsets
    const int a_lrow = lane & 15;
    const int a_lcol = (lane >> 4) * 4;
    const int b_lrow = (lane & 7) + ((lane >> 4) << 3);
    const int b_lcol = ((lane >> 3) & 1) * 4;

    const uint32_t ash_b = smem_u32(ash), asl_b = smem_u32(asl);
    const uint32_t bsh_b = smem_u32(bsh), bsl_b = smem_u32(bsl);

    float acc[4][4][4];
    #pragma unroll
    for (int i = 0; i < 4; i++)
        #pragma unroll
        for (int j = 0; j < 4; j++)
            #pragma unroll
            for (int r = 0; r < 4; r++) acc[i][j][r] = 0.f;

    const int nk = K >> 4;

    // prologue: tile 0 -> stage 0
    {
        uint4 vah = *reinterpret_cast<const uint4*>(Ah + (size_t)(m0 + rowa) * K2 + hw);
        uint4 val = *reinterpret_cast<const uint4*>(Al + (size_t)(m0 + rowa) * K2 + hw);
        uint4 vbh = *reinterpret_cast<const uint4*>(Bh + (size_t)(n0 + rowa) * K2 + hw);
        uint4 vbl = *reinterpret_cast<const uint4*>(Bl + (size_t)(n0 + rowa) * K2 + hw);
        *reinterpret_cast<uint4*>(&ash[0][rowa*S + hw]) = vah;
        *reinterpret_cast<uint4*>(&asl[0][rowa*S + hw]) = val;
        *reinterpret_cast<uint4*>(&bsh[0][rowa*S + hw]) = vbh;
        *reinterpret_cast<uint4*>(&bsl[0][rowa*S + hw]) = vbl;
    }
    __syncthreads();

    for (int kt = 0; kt < nk; kt++) {
        const int cur = kt & 1, nxt = cur ^ 1;
        uint4 pah, pal, pbh, pbl;
        if (kt + 1 < nk) {
            int ko = (kt + 1) * 8 + hw;
            pah = *reinterpret_cast<const uint4*>(Ah + (size_t)(m0 + rowa) * K2 + ko);
            pal = *reinterpret_cast<const uint4*>(Al + (size_t)(m0 + rowa) * K2 + ko);
            pbh = *reinterpret_cast<const uint4*>(Bh + (size_t)(n0 + rowa) * K2 + ko);
            pbl = *reinterpret_cast<const uint4*>(Bl + (size_t)(n0 + rowa) * K2 + ko);
        }

        {
            uint32_t ah[4][4], al[4][4], bh2[4][2], bl2[4][2];
            #pragma unroll
            for (int mi = 0; mi < 4; mi++) {
                uint32_t woff = ((cur*128 + wm0 + mi*16 + a_lrow) * S + a_lcol) * 4;
                ldsm4(ah[mi], ash_b + woff);
                ldsm4(al[mi], asl_b + woff);
            }
            #pragma unroll
            for (int p = 0; p < 2; p++) {
                uint32_t woff = ((cur*128 + wn0 + p*16 + b_lrow) * S + b_lcol) * 4;
                uint32_t r[4];
                ldsm4(r, bsh_b + woff);
                bh2[2*p][0] = r[0]; bh2[2*p][1] = r[1];
                bh2[2*p+1][0] = r[2]; bh2[2*p+1][1] = r[3];
                ldsm4(r, bsl_b + woff);
                bl2[2*p][0] = r[0]; bl2[2*p][1] = r[1];
                bl2[2*p+1][0] = r[2]; bl2[2*p+1][1] = r[3];
            }
            #pragma unroll
            for (int mi = 0; mi < 4; mi++)
                #pragma unroll
                for (int ni = 0; ni < 4; ni++) {
                    mma_bf16(acc[mi][ni], ah[mi], bh2[ni]);
                    mma_bf16(acc[mi][ni], ah[mi], bl2[ni]);
                    mma_bf16(acc[mi][ni], al[mi], bh2[ni]);
                }
        }

        if (kt + 1 < nk) {
            *reinterpret_cast<uint4*>(&ash[nxt][rowa*S + hw]) = pah;
            *reinterpret_cast<uint4*>(&asl[nxt][rowa*S + hw]) = pal;
            *reinterpret_cast<uint4*>(&bsh[nxt][rowa*S + hw]) = pbh;
            *reinterpret_cast<uint4*>(&bsl[nxt][rowa*S + hw]) = pbl;
            __syncthreads();
        }
    }

    // epilogue
    #pragma unroll
    for (int mi = 0; mi < 4; mi++) {
        #pragma unroll
        for (int ni = 0; ni < 4; ni++) {
            long long row0 = m0 + wm0 + mi * 16 + g;
            int col = n0 + wn0 + ni * 8 + tg * 2;
            if (OUT == 0) {
                *reinterpret_cast<float2*>(&C[row0 * N + col]) =
                    make_float2(acc[mi][ni][0], acc[mi][ni][1]);
                *reinterpret_cast<float2*>(&C[(row0 + 8) * N + col]) =
                    make_float2(acc[mi][ni][2], acc[mi][ni][3]);
            } else {
                float r[4];
                #pragma unroll
                for (int t = 0; t < 4; t++) {
                    float v = acc[mi][ni][t];
                    r[t] = 0.5f * v * (1.0f + erff(v * 0.70710678118654752f));
                }
                uint32_t h0, l0, h1, l1;
                cvt_hl(r[0], r[1], h0, l0);
                cvt_hl(r[2], r[3], h1, l1);
                size_t w0 = (size_t)(row0 * N + col) >> 1;
                size_t w1 = (size_t)((row0 + 8) * N + col) >> 1;
                Oh[w0] = h0; Ol[w0] = l0;
                Oh[w1] = h1; Ol[w1] = l1;
            }
        }
    }
}

// ---------------- fused flash attention (bf16x3, online softmax) ----------------
#define FA_SK 36
__global__ __launch_bounds__(256)
void k_flash(const float* __restrict__ qp, const float* __restrict__ kp,
             const float* __restrict__ vpT, float* __restrict__ Og, int Tk)
{
    __shared__ uint32_t khw[64*FA_SK], klw[64*FA_SK];
    __shared__ uint32_t vhw[64*FA_SK], vlw[64*FA_SK];

    const int nh = blockIdx.y;
    const int q0 = blockIdx.x * 128;
    const int tid = threadIdx.x, wid = tid >> 5, lane = tid & 31;
    const int g = lane >> 2, tg = lane & 3;

    const float* Qb = qp + ((size_t)nh * LTOK + q0) * HD;
    const float* Kb = kp + (size_t)nh * Tk * HD;
    const float* Vb = vpT + (size_t)nh * HD * Tk;

    const int row0 = wid * 16 + g;
    uint32_t qh[4][4], ql[4][4];
    #pragma unroll
    for (int kk = 0; kk < 4; kk++) {
        int col = kk * 16 + tg * 2;
        float2 q00 = *reinterpret_cast<const float2*>(&Qb[(size_t)row0 * HD + col]);
        float2 q01 = *reinterpret_cast<const float2*>(&Qb[(size_t)row0 * HD + col + 8]);
        float2 q10 = *reinterpret_cast<const float2*>(&Qb[(size_t)(row0 + 8) * HD + col]);
        float2 q11 = *reinterpret_cast<const float2*>(&Qb[(size_t)(row0 + 8) * HD + col + 8]);
        cvt_hl(q00.x * 0.125f, q00.y * 0.125f, qh[kk][0], ql[kk][0]);
        cvt_hl(q10.x * 0.125f, q10.y * 0.125f, qh[kk][1], ql[kk][1]);
        cvt_hl(q01.x * 0.125f, q01.y * 0.125f, qh[kk][2], ql[kk][2]);
        cvt_hl(q11.x * 0.125f, q11.y * 0.125f, qh[kk][3], ql[kk][3]);
    }

    float m0 = -1e30f, m1 = -1e30f, l0 = 0.f, l1 = 0.f;
    float oacc[8][4];
    #pragma unroll
    for (int i = 0; i < 8; i++)
        #pragma unroll
        for (int t = 0; t < 4; t++) oacc[i][t] = 0.f;

    for (int kv0 = 0; kv0 < Tk; kv0 += 64) {
        {
            int r = tid >> 2, c = (tid & 3) * 16;
            const float* sk = Kb + (size_t)(kv0 + r) * HD + c;
            const float* sv = Vb + (size_t)r * Tk + kv0 + c;
            #pragma unroll
            for (int j = 0; j < 4; j++) {
                float4 kv = *reinterpret_cast<const float4*>(sk + j * 4);
                float4 vv = *reinterpret_cast<const float4*>(sv + j * 4);
                int w = r * FA_SK + (c >> 1) + j * 2;
                uint32_t h, l;
                cvt_hl(kv.x, kv.y, h, l); khw[w] = h;   klw[w] = l;
                cvt_hl(kv.z, kv.w, h, l); khw[w+1] = h; klw[w+1] = l;
                cvt_hl(vv.x, vv.y, h, l); vhw[w] = h;   vlw[w] = l;
                cvt_hl(vv.z, vv.w, h, l); vhw[w+1] = h; vlw[w+1] = l;
            }
        }
        __syncthreads();

        float sacc[8][4];
        #pragma unroll
        for (int i = 0; i < 8; i++)
            #pragma unroll
            for (int t = 0; t < 4; t++) sacc[i][t] = 0.f;
        #pragma unroll
        for (int kk = 0; kk < 4; kk++) {
            #pragma unroll
            for (int ni = 0; ni < 8; ni++) {
                uint32_t bh[2], bl[2];
                int off = (ni * 8 + g) * FA_SK + kk * 8 + tg;
                bh[0] = khw[off]; bh[1] = khw[off + 4];
                bl[0] = klw[off]; bl[1] = klw[off + 4];
                mma_bf16(sacc[ni], qh[kk], bh);
                mma_bf16(sacc[ni], qh[kk], bl);
                mma_bf16(sacc[ni], ql[kk], bh);
            }
        }

        float mx0 = -1e30f, mx1 = -1e30f;
        #pragma unroll
        for (int ni = 0; ni < 8; ni++) {
            mx0 = fmaxf(mx0, fmaxf(sacc[ni][0], sacc[ni][1]));
            mx1 = fmaxf(mx1, fmaxf(sacc[ni][2], sacc[ni][3]));
        }
        mx0 = fmaxf(mx0, __shfl_xor_sync(0xffffffff, mx0, 1));
        mx0 = fmaxf(mx0, __shfl_xor_sync(0xffffffff, mx0, 2));
        mx1 = fmaxf(mx1, __shfl_xor_sync(0xffffffff, mx1, 1));
        mx1 = fmaxf(mx1, __shfl_xor_sync(0xffffffff, mx1, 2));
        float nm0 = fmaxf(m0, mx0), nm1 = fmaxf(m1, mx1);
        float al0 = __expf(m0 - nm0), al1 = __expf(m1 - nm1);
        float rs0 = 0.f, rs1 = 0.f;
        #pragma unroll
        for (int ni = 0; ni < 8; ni++) {
            sacc[ni][0] = __expf(sacc[ni][0] - nm0);
            sacc[ni][1] = __expf(sacc[ni][1] - nm0);
            sacc[ni][2] = __expf(sacc[ni][2] - nm1);
            sacc[ni][3] = __expf(sacc[ni][3] - nm1);
            rs0 += sacc[ni][0] + sacc[ni][1];
            rs1 += sacc[ni][2] + sacc[ni][3];
        }
        rs0 += __shfl_xor_sync(0xffffffff, rs0, 1);
        rs0 += __shfl_xor_sync(0xffffffff, rs0, 2);
        rs1 += __shfl_xor_sync(0xffffffff, rs1, 1);
        rs1 += __shfl_xor_sync(0xffffffff, rs1, 2);
        l0 = l0 * al0 + rs0;  l1 = l1 * al1 + rs1;
        m0 = nm0;  m1 = nm1;
        #pragma unroll
        for (int nd = 0; nd < 8; nd++) {
            oacc[nd][0] *= al0; oacc[nd][1] *= al0;
            oacc[nd][2] *= al1; oacc[nd][3] *= al1;
        }

        #pragma unroll
        for (int kk = 0; kk < 4; kk++) {
            uint32_t ph[4], pl[4];
            cvt_hl(sacc[2*kk][0],   sacc[2*kk][1],   ph[0], pl[0]);
            cvt_hl(sacc[2*kk][2],   sacc[2*kk][3],   ph[1], pl[1]);
            cvt_hl(sacc[2*kk+1][0], sacc[2*kk+1][1], ph[2], pl[2]);
            cvt_hl(sacc[2*kk+1][2], sacc[2*kk+1][3], ph[3], pl[3]);
            #pragma unroll
            for (int nd = 0; nd < 8; nd++) {
                uint32_t vh[2], vl[2];
                int off = (nd * 8 + g) * FA_SK + kk * 8 + tg;
                vh[0] = vhw[off]; vh[1] = vhw[off + 4];
                vl[0] = vlw[off]; vl[1] = vlw[off + 4];
                mma_bf16(oacc[nd], ph, vh);
                mma_bf16(oacc[nd], ph, vl);
                mma_bf16(oacc[nd], pl, vh);
            }
        }
        __syncthreads();
    }

    float il0 = 1.0f / l0, il1 = 1.0f / l1;
    float* Ob = Og + ((size_t)nh * LTOK + q0) * HD;
    #pragma unroll
    for (int nd = 0; nd < 8; nd++) {
        int col = nd * 8 + tg * 2;
        *reinterpret_cast<float2*>(&Ob[(size_t)row0 * HD + col]) =
            make_float2(oacc[nd][0] * il0, oacc[nd][1] * il0);
        *reinterpret_cast<float2*>(&Ob[(size_t)(row0 + 8) * HD + col]) =
            make_float2(oacc[nd][2] * il1, oacc[nd][3] * il1);
    }
}

// ---------------- layout kernels ----------------
// features [n][c][l] -> x [n][l][c] fp32 + hi/lo words
__global__ void k_build_x(const float* __restrict__ f, float* __restrict__ x,
                          uint32_t* __restrict__ xh, uint32_t* __restrict__ xl) {
    int idx = blockIdx.x * blockDim.x + threadIdx.x;   // word index
    if (idx >= XW) return;
    int c2 = idx & 127;
    int l  = (idx >> 7) & (LTOK-1);
    int n  = idx >> 17;
    int c  = c2 * 2;
    float a = f[((size_t)n*CC + c)*LTOK + l];
    float b = f[((size_t)n*CC + c + 1)*LTOK + l];
    reinterpret_cast<float2*>(x)[idx] = make_float2(a, b);
    uint32_t h, lw;
    cvt_hl(a, b, h, lw);
    xh[idx] = h; xl[idx] = lw;
}

__global__ void k_final(const float* __restrict__ x, float* __restrict__ o) {
    int idx = blockIdx.x * blockDim.x + threadIdx.x;
    if (idx >= NVB*LTOK*CC) return;
    int l = idx & (LTOK-1);
    int c = (idx >> 10) & (CC-1);
    int n = idx >> 18;
    o[idx] = x[((size_t)n*LTOK + l)*CC + c];
}

// ---------------- PRoPE matrix build ----------------
__device__ __forceinline__ void prope_forward(const float* vm, const float* Kc,
                                              float u, float vyy, float* M) {
    float fx = Kc[0] * (1.0f/128.0f), fy = Kc[4] * (1.0f/128.0f);
    float cx = Kc[2] * (1.0f/128.0f), cy = Kc[5] * (1.0f/128.0f);
    float a = cx - u, b = cy - vyy;
    #pragma unroll
    for (int c = 0; c < 4; c++) {
        M[0*4+c] = fx*vm[0*4+c] + a*vm[2*4+c];
        M[1*4+c] = fy*vm[1*4+c] + b*vm[2*4+c];
        M[2*4+c] = vm[2*4+c];
        M[3*4+c] = vm[3*4+c];
    }
}

__global__ void k_prope_q(const float* __restrict__ vms, const float* __restrict__ Ks,
                          float* __restrict__ Mq, float* __restrict__ Mqi) {
    int idx = blockIdx.x * blockDim.x + threadIdx.x;
    if (idx >= NVB*LTOK) return;
    int n = idx >> 10, t = idx & (LTOK-1);
    int px = t & 31, py = t >> 5;
    float u  = (px + 0.5f) * (1.0f/32.0f);
    float vy = (py + 0.5f) * (1.0f/32.0f);
    const float* vm = vms + n*16;
    const float* Kc = Ks + n*9;
    float M[16];
    prope_forward(vm, Kc, u, vy, M);
    #pragma unroll
    for (int i = 0; i < 16; i++) Mq[idx*16+i] = M[i];

    float r00=vm[0],r01=vm[1],r02=vm[2],  t0=vm[3];
    float r10=vm[4],r11=vm[5],r12=vm[6],  t1=vm[7];
    float r20=vm[8],r21=vm[9],r22=vm[10], t2=vm[11];
    float det = r00*(r11*r22-r12*r21) - r01*(r10*r22-r12*r20) + r02*(r10*r21-r11*r20);
    float id = 1.0f/det;
    float Ri[9];
    Ri[0]=(r11*r22-r12*r21)*id; Ri[1]=(r02*r21-r01*r22)*id; Ri[2]=(r01*r12-r02*r11)*id;
    Ri[3]=(r12*r20-r10*r22)*id; Ri[4]=(r00*r22-r02*r20)*id; Ri[5]=(r02*r10-r00*r12)*id;
    Ri[6]=(r10*r21-r11*r20)*id; Ri[7]=(r01*r20-r00*r21)*id; Ri[8]=(r00*r11-r01*r10)*id;
    float ti0 = -(Ri[0]*t0 + Ri[1]*t1 + Ri[2]*t2);
    float ti1 = -(Ri[3]*t0 + Ri[4]*t1 + Ri[5]*t2);
    float ti2 = -(Ri[6]*t0 + Ri[7]*t1 + Ri[8]*t2);
    float fx = Kc[0]*(1.0f/128.0f), fy = Kc[4]*(1.0f/128.0f);
    float cx = Kc[2]*(1.0f/128.0f), cy = Kc[5]*(1.0f/128.0f);
    float a = cx - u, b = cy - vy;
    float ifx = 1.0f/fx, ify = 1.0f/fy;
    float Mi[16];
    float tv[3] = {ti0, ti1, ti2};
    #pragma unroll
    for (int i = 0; i < 3; i++) {
        Mi[i*4+0] = Ri[i*3+0]*ifx;
        Mi[i*4+1] = Ri[i*3+1]*ify;
        Mi[i*4+2] = -Ri[i*3+0]*a*ifx - Ri[i*3+1]*b*ify + Ri[i*3+2];
        Mi[i*4+3] = tv[i];
    }
    Mi[12]=0.f; Mi[13]=0.f; Mi[14]=0.f; Mi[15]=1.f;
    #pragma unroll
    for (int i = 0; i < 16; i++) Mqi[idx*16+i] = Mi[i];
}

__global__ void k_prope_kv(const float* __restrict__ vms, const float* __restrict__ Ks,
                           float* __restrict__ Mkv) {
    int idx = blockIdx.x * blockDim.x + threadIdx.x;
    if (idx >= NVB*TKX) return;
    int n = idx >> 11, tt = idx & (TKX-1);
    int m = tt >> 10, l = tt & (LTOK-1);
    int vvi = n >> 1, b = n & 1;
    int j = m + (m >= vvi ? 1 : 0);
    int cam = j*BB + b;
    int px = l & 31, py = l >> 5;
    float u  = (px + 0.5f)*(1.0f/32.0f);
    float vy = (py + 0.5f)*(1.0f/32.0f);
    float M[16];
    prope_forward(vms + cam*16, Ks + cam*9, u, vy, M);
    #pragma unroll
    for (int i = 0; i < 16; i++) Mkv[idx*16+i] = M[i];
}

// ---------------- per-token 4x4 projective applies ----------------
__global__ void k_apply_q(const float* __restrict__ q, const float* __restrict__ Mi,
                          float* __restrict__ qp) {
    int idx = blockIdx.x * blockDim.x + threadIdx.x;
    if (idx >= NVB*LTOK*NH*16) return;
    int g = idx & 15, h = (idx >> 4) & 3, t = (idx >> 6) & (LTOK-1), n = idx >> 16;
    const float* M = Mi + ((size_t)(n*LTOK + t))*16;
    const float* s = q + ((size_t)(n*LTOK + t))*CC + h*HD + g*4;
    float x0=s[0], x1=s[1], x2=s[2], x3=s[3];
    float* d = qp + (((size_t)(n*NH + h))*LTOK + t)*HD + g*4;
    #pragma unroll
    for (int i = 0; i < 4; i++)
        d[i] = M[0*4+i]*x0 + M[1*4+i]*x1 + M[2*4+i]*x2 + M[3*4+i]*x3;
}

__global__ void k_apply_kv(const float* __restrict__ ks, const float* __restrict__ Mats,
                           float* __restrict__ kp, int Tk, int gather) {
    int idx = blockIdx.x * blockDim.x + threadIdx.x;
    if (idx >= NVB*Tk*NH*16) return;
    int g = idx & 15, h = (idx >> 4) & 3;
    int tt = (idx >> 6) % Tk, n = (idx >> 6) / Tk;
    size_t srcRow;
    if (gather) {
        int m = tt >> 10, l = tt & (LTOK-1);
        int vvi = n >> 1, b = n & 1;
        int j = m + (m >= vvi ? 1 : 0);
        srcRow = (size_t)(j*BB + b)*LTOK + l;
    } else {
        srcRow = (size_t)n*LTOK + tt;
    }
    const float* M = Mats + ((size_t)n*Tk + tt)*16;
    const float* s = ks + srcRow*CC + h*HD + g*4;
    float x0=s[0], x1=s[1], x2=s[2], x3=s[3];
    float* d = kp + (((size_t)(n*NH + h))*Tk + tt)*HD + g*4;
    #pragma unroll
    for (int i = 0; i < 4; i++)
        d[i] = M[i*4+0]*x0 + M[i*4+1]*x1 + M[i*4+2]*x2 + M[i*4+3]*x3;
}

__global__ void k_apply_v_t(const float* __restrict__ vs, const float* __restrict__ Mats,
                            float* __restrict__ vpT, int Tk, int gather) {
    int idx = blockIdx.x * blockDim.x + threadIdx.x;
    if (idx >= NVB*NH*16*Tk) return;
    int tt = idx % Tk;
    int rest = idx / Tk;
    int g = rest & 15, h = (rest >> 4) & 3, n = rest >> 6;
    size_t srcRow;
    if (gather) {
        int m = tt >> 10, l = tt & (LTOK-1);
        int vvi = n >> 1, b = n & 1;
        int j = m + (m >= vvi ? 1 : 0);
        srcRow = (size_t)(j*BB + b)*LTOK + l;
    } else {
        srcRow = (size_t)n*LTOK + tt;
    }
    const float* M = Mats + ((size_t)n*Tk + tt)*16;
    const float* s = vs + srcRow*CC + h*HD + g*4;
    float x0=s[0], x1=s[1], x2=s[2], x3=s[3];
    float* dbase = vpT + ((size_t)(n*NH + h)*HD + g*4)*Tk + tt;
    #pragma unroll
    for (int i = 0; i < 4; i++)
        dbase[(size_t)i*Tk] = M[i*4+0]*x0 + M[i*4+1]*x1 + M[i*4+2]*x2 + M[i*4+3]*x3;
}

// om written directly as bf16 hi/lo words (only used as GEMM A operand)
__global__ void k_apply_out(const float* __restrict__ O, const float* __restrict__ Mi,
                            uint32_t* __restrict__ omh, uint32_t* __restrict__ oml) {
    int idx = blockIdx.x * blockDim.x + threadIdx.x;
    if (idx >= NVB*LTOK*NH*16) return;
    int g = idx & 15, h = (idx >> 4) & 3, t = (idx >> 6) & (LTOK-1), n = idx >> 16;
    const float* M = Mi + ((size_t)(n*LTOK + t))*16;
    const float* s = O + (((size_t)(n*NH + h))*LTOK + t)*HD + g*4;
    float x0=s[0], x1=s[1], x2=s[2], x3=s[3];
    float d[4];
    #pragma unroll
    for (int i = 0; i < 4; i++)
        d[i] = M[i*4+0]*x0 + M[i*4+1]*x1 + M[i*4+2]*x2 + M[i*4+3]*x3;
    size_t w = (((size_t)(n*LTOK + t))*CC + h*HD + g*4) >> 1;
    uint32_t h0, l0, h1, l1;
    cvt_hl(d[0], d[1], h0, l0);
    cvt_hl(d[2], d[3], h1, l1);
    omh[w] = h0;   oml[w] = l0;
    omh[w+1] = h1; oml[w+1] = l1;
}

// ---------------- layernorm (+optional residual add, optional hi/lo out) ----
__global__ void k_ln(float* __restrict__ dst, const float* __restrict__ src,
                     const float* __restrict__ w, const float* __restrict__ b, int add,
                     uint32_t* __restrict__ oh, uint32_t* __restrict__ ol) {
    __shared__ float red[256];
    int row = blockIdx.x, tid = threadIdx.x;
    float v = src[(size_t)row*CC + tid];
    red[tid] = v; __syncthreads();
    for (int s = 128; s > 0; s >>= 1) { if (tid < s) red[tid] += red[tid+s]; __syncthreads(); }
    float mu = red[0] * (1.0f/CC); __syncthreads();
    float d = v - mu;
    red[tid] = d * d; __syncthreads();
    for (int s = 128; s > 0; s >>= 1) { if (tid < s) red[tid] += red[tid+s]; __syncthreads(); }
    float var = red[0] * (1.0f/CC);
    float o = d * rsqrtf(var + 1e-5f) * w[tid] + b[tid];
    float fin;
    if (add) { fin = dst[(size_t)row*CC + tid] + o; dst[(size_t)row*CC + tid] = fin; }
    else     { fin = o; dst[(size_t)row*CC + tid] = fin; }
    if (oh) {
        __syncthreads();
        red[tid] = fin;
        __syncthreads();
        if (tid < 128) {
            uint32_t h, l;
            cvt_hl(red[2*tid], red[2*tid+1], h, l);
            oh[(size_t)row*(CC/2) + tid] = h;
            ol[(size_t)row*(CC/2) + tid] = l;
        }
    }
}

// ---------------- concat -> bf16 hi/lo (W1 A operand) ----------------
__global__ void k_cat(const float* __restrict__ x, const float* __restrict__ msg,
                      uint32_t* __restrict__ ch, uint32_t* __restrict__ cl) {
    int idx = blockIdx.x * blockDim.x + threadIdx.x;   // word over rows*256
    if (idx >= ROWS_*(FFNI/2)) return;
    int c2 = idx & 255, row = idx >> 8;
    float2 v;
    if (c2 < 128) v = reinterpret_cast<const float2*>(x + (size_t)row*CC)[c2];
    else          v = reinterpret_cast<const float2*>(msg + (size_t)row*CC)[c2 - 128];
    uint32_t h, l;
    cvt_hl(v.x, v.y, h, l);
    ch[idx] = h; cl[idx] = l;
}

// ---------------- host driver ----------------
static void gemm2(const uint32_t* Ah, const uint32_t* Al,
                  const uint32_t* Bh, const uint32_t* Bl,
                  float* C, int M, int N, int K) {
    dim3 g(N/128, M/128);
    tc_gemm2<0><<<g, 256>>>(Ah, Al, Bh, Bl, C, nullptr, nullptr, M, N, K);
}
static void gemm2_gelu_hl(const uint32_t* Ah, const uint32_t* Al,
                          const uint32_t* Bh, const uint32_t* Bl,
                          uint32_t* Oh, uint32_t* Ol, int M, int N, int K) {
    dim3 g(N/128, M/128);
    tc_gemm2<1><<<g, 256>>>(Ah, Al, Bh, Bl, nullptr, Oh, Ol, M, N, K);
}

extern "C" void kernel_launch(void* const* d_in, const int* in_sizes, int n_in,
                              void* d_out, int out_size) {
    const float* feats = (const float*)d_in[0];
    const float* vms   = (const float*)d_in[1];
    const float* Ks    = (const float*)d_in[2];
    const float* Wq    = (const float*)d_in[3];
    const float* Wk    = (const float*)d_in[4];
    const float* Wv    = (const float*)d_in[5];
    const float* Wm    = (const float*)d_in[6];
    const float* n1w   = (const float*)d_in[7];
    const float* n1b   = (const float*)d_in[8];
    const float* W1    = (const float*)d_in[9];
    const float* W2    = (const float*)d_in[10];
    const float* n2w   = (const float*)d_in[11];
    const float* n2b   = (const float*)d_in[12];

    void* p;
    float *x,*q,*k,*v,*qp,*kp,*vp,*O,*msg,*h2,*Mq,*Mqi,*Mkv;
    uint32_t *xh,*xl,*xpreh,*xprel,*omh,*oml,*cath,*catl,*hh,*hl,*wh,*wl;
    cudaGetSymbolAddress(&p, g_x);    x   = (float*)p;
    cudaGetSymbolAddress(&p, g_q);    q   = (float*)p;
    cudaGetSymbolAddress(&p, g_k);    k   = (float*)p;
    cudaGetSymbolAddress(&p, g_v);    v   = (float*)p;
    cudaGetSymbolAddress(&p, g_qp);   qp  = (float*)p;
    cudaGetSymbolAddress(&p, g_kp);   kp  = (float*)p;
    cudaGetSymbolAddress(&p, g_vp);   vp  = (float*)p;
    cudaGetSymbolAddress(&p, g_O);    O   = (float*)p;
    cudaGetSymbolAddress(&p, g_msg);  msg = (float*)p;
    cudaGetSymbolAddress(&p, g_h2);   h2  = (float*)p;
    cudaGetSymbolAddress(&p, g_Mq);   Mq  = (float*)p;
    cudaGetSymbolAddress(&p, g_Mqi);  Mqi = (float*)p;
    cudaGetSymbolAddress(&p, g_Mkv);  Mkv = (float*)p;
    cudaGetSymbolAddress(&p, g_xh);    xh    = (uint32_t*)p;
    cudaGetSymbolAddress(&p, g_xl);    xl    = (uint32_t*)p;
    cudaGetSymbolAddress(&p, g_xpreh); xpreh = (uint32_t*)p;
    cudaGetSymbolAddress(&p, g_xprel); xprel = (uint32_t*)p;
    cudaGetSymbolAddress(&p, g_omh);   omh   = (uint32_t*)p;
    cudaGetSymbolAddress(&p, g_oml);   oml   = (uint32_t*)p;
    cudaGetSymbolAddress(&p, g_cath);  cath  = (uint32_t*)p;
    cudaGetSymbolAddress(&p, g_catl);  catl  = (uint32_t*)p;
    cudaGetSymbolAddress(&p, g_hh);    hh    = (uint32_t*)p;
    cudaGetSymbolAddress(&p, g_hl);    hl    = (uint32_t*)p;
    cudaGetSymbolAddress(&p, g_wh);    wh    = (uint32_t*)p;
    cudaGetSymbolAddress(&p, g_wl);    wl    = (uint32_t*)p;

    const int ROWS = ROWS_;
    const int NEL  = ROWS * CC;

    // weight preconversion (word counts)
    k_cvt<<<(131072+255)/256, 256>>>(Wq, wh+WQO, wl+WQO, 131072);
    k_cvt<<<(131072+255)/256, 256>>>(Wk, wh+WKO, wl+WKO, 131072);
    k_cvt<<<(131072+255)/256, 256>>>(Wv, wh+WVO, wl+WVO, 131072);
    k_cvt<<<(131072+255)/256, 256>>>(Wm, wh+WMO, wl+WMO, 131072);
    k_cvt<<<(1048576+255)/256, 256>>>(W1, wh+W1O, wl+W1O, 1048576);
    k_cvt<<<(524288+255)/256, 256>>>(W2, wh+W2O, wl+W2O, 524288);

    k_build_x<<<(XW+255)/256, 256>>>(feats, x, xh, xl);
    k_prope_q<<<(ROWS+255)/256, 256>>>(vms, Ks, Mq, Mqi);
    k_prope_kv<<<(NVB*TKX+255)/256, 256>>>(vms, Ks, Mkv);

    for (int ly = 0; ly < 2; ly++) {
        const uint32_t wo0 = (uint32_t)(ly*2+0) * 32768;   // 256*256/2 words
        const uint32_t wo1 = (uint32_t)(ly*2+1) * 32768;

        // snapshot x (pre-self-attn) as cross-attn KV source (hi/lo only)
        k_cvt<<<(XW+255)/256, 256>>>(x, xpreh, xprel, XW);

        // ---------- self attention ----------
        gemm2(xh, xl, wh+WQO+wo0, wl+WQO+wo0, q, ROWS, CC, CC);
        gemm2(xh, xl, wh+WKO+wo0, wl+WKO+wo0, k, ROWS, CC, CC);
        gemm2(xh, xl, wh+WVO+wo0, wl+WVO+wo0, v, ROWS, CC, CC);
        k_apply_q  <<<(NVB*LTOK*NH*16)/256, 256>>>(q, Mqi, qp);
        k_apply_kv <<<(NVB*LTOK*NH*16)/256, 256>>>(k, Mq, kp, LTOK, 0);
        k_apply_v_t<<<(NVB*LTOK*NH*16)/256, 256>>>(v, Mq, vp, LTOK, 0);
        k_flash<<<dim3(LTOK/128, NVB*NH), 256>>>(qp, kp, vp, O, LTOK);
        k_apply_out<<<(NVB*LTOK*NH*16)/256, 256>>>(O, Mqi, omh, oml);
        gemm2(omh, oml, wh+WMO+wo0, wl+WMO+wo0, msg, ROWS, CC, CC);
        k_ln<<<ROWS, 256>>>(x, msg, n1w + (ly*2+0)*CC, n1b + (ly*2+0)*CC, 1, xh, xl);

        // ---------- cross attention ----------
        gemm2(xh,    xl,    wh+WQO+wo1, wl+WQO+wo1, q, ROWS, CC, CC);
        gemm2(xpreh, xprel, wh+WKO+wo1, wl+WKO+wo1, k, ROWS, CC, CC);
        gemm2(xpreh, xprel, wh+WVO+wo1, wl+WVO+wo1, v, ROWS, CC, CC);
        k_apply_q  <<<(NVB*LTOK*NH*16)/256, 256>>>(q, Mqi, qp);
        k_apply_kv <<<(NVB*TKX*NH*16)/256, 256>>>(k, Mkv, kp, TKX, 1);
        k_apply_v_t<<<(NVB*TKX*NH*16)/256, 256>>>(v, Mkv, vp, TKX, 1);
        k_flash<<<dim3(LTOK/128, NVB*NH), 256>>>(qp, kp, vp, O, TKX);
        k_apply_out<<<(NVB*LTOK*NH*16)/256, 256>>>(O, Mqi, omh, oml);
        gemm2(omh, oml, wh+WMO+wo1, wl+WMO+wo1, msg, ROWS, CC, CC);
        k_ln<<<ROWS, 256>>>(msg, msg, n1w + (ly*2+1)*CC, n1b + (ly*2+1)*CC, 0,
                            nullptr, nullptr);

        // ---------- FFN ----------
        k_cat<<<(ROWS*(FFNI/2))/256, 256>>>(x, msg, cath, catl);
        gemm2_gelu_hl(cath, catl, wh+W1O + (size_t)ly*524288, wl+W1O + (size_t)ly*524288,
                      hh, hl, ROWS, FFNH, FFNI);
        gemm2(hh, hl, wh+W2O + (size_t)ly*262144, wl+W2O + (size_t)ly*262144,
              h2, ROWS, CC, FFNH);
        k_ln<<<ROWS, 256>>>(x, h2, n2w + ly*CC, n2b + ly*CC, 1, xh, xl);
    }

    k_final<<<(NEL+255)/256, 256>>>(x, (float*)d_out);
}

// round 8
// speedup vs baseline: 1.9846x; 1.0315x over previous
#include <cuda_runtime.h>
#include <cuda_bf16.h>
#include <math.h>
#include <stdint.h>

// ---------------- problem constants ----------------
#define NVB   6
#define VV    3
#define BB    2
#define CC    256
#define LTOK  1024
#define TKX   2048
#define NH    4
#define HD    64
#define FFNI  512
#define FFNH  2048

#define ROWS_ (NVB*LTOK)          // 6144
#define XW    (NVB*LTOK*CC/2)     // words in x hi/lo

// ---------------- device scratch ----------------
__device__ float g_x   [ROWS_*CC];
__device__ float g_qkv [ROWS_*768];           // self-attn fused Q|K|V
__device__ float g_q   [ROWS_*CC];            // cross-attn Q
__device__ float g_kvb [ROWS_*512];           // cross-attn K|V
__device__ float g_qp  [NVB*NH*LTOK*HD];
__device__ float g_kp  [NVB*NH*TKX*HD];
__device__ float g_vp  [NVB*NH*TKX*HD];       // TRANSPOSED: [n][h][HD][Tk]
__device__ float g_O   [NVB*NH*LTOK*HD];
__device__ float g_msg [ROWS_*CC];
__device__ float g_h2  [ROWS_*CC];
__device__ float g_Mq  [NVB*LTOK*16];
__device__ float g_Mqi [NVB*LTOK*16];
__device__ float g_Mkv [NVB*TKX*16];

// packed bf16 hi/lo operand buffers
__device__ uint32_t g_xh   [XW],  g_xl   [XW];
__device__ uint32_t g_xpreh[XW],  g_xprel[XW];
__device__ uint32_t g_omh  [XW],  g_oml  [XW];
__device__ uint32_t g_cath [ROWS_*FFNI/2], g_catl[ROWS_*FFNI/2];
__device__ uint32_t g_hh   [ROWS_*FFNH/2], g_hl  [ROWS_*FFNH/2];
// weights (words): wqkv_self 2x98304 | wq_x 2x32768 | wkv_x 2x65536 | wm 4x32768 | w1 | w2
#define WQKV0 0
#define WQX0  196608
#define WKVX0 262144
#define WMO   393216
#define W1O   524288
#define W2O   1572864
__device__ uint32_t g_wh[2097152], g_wl[2097152];

// ---------------- helpers ----------------
__device__ __forceinline__ void cvt_hl(float x, float y, uint32_t& hi, uint32_t& lo) {
    __nv_bfloat162 h = __floats2bfloat162_rn(x, y);
    float rx = x - __bfloat162float(h.x);
    float ry = y - __bfloat162float(h.y);
    __nv_bfloat162 l = __floats2bfloat162_rn(rx, ry);
    hi = *reinterpret_cast<uint32_t*>(&h);
    lo = *reinterpret_cast<uint32_t*>(&l);
}

__device__ __forceinline__ void mma_bf16(float* c, const uint32_t* a, const uint32_t* b) {
    asm volatile(
        "mma.sync.aligned.m16n8k16.row.col.f32.bf16.bf16.f32 "
        "{%0,%1,%2,%3}, {%4,%5,%6,%7}, {%8,%9}, {%0,%1,%2,%3};"
        : "+f"(c[0]), "+f"(c[1]), "+f"(c[2]), "+f"(c[3])
        : "r"(a[0]), "r"(a[1]), "r"(a[2]), "r"(a[3]), "r"(b[0]), "r"(b[1]));
}

__device__ __forceinline__ void ldsm4(uint32_t* r, uint32_t addr) {
    asm volatile("ldmatrix.sync.aligned.m8n8.x4.shared.b16 {%0,%1,%2,%3}, [%4];"
        : "=r"(r[0]), "=r"(r[1]), "=r"(r[2]), "=r"(r[3]) : "r"(addr));
}

__device__ __forceinline__ uint32_t smem_u32(const void* p) {
    uint32_t a;
    asm("{ .reg .u64 t; cvta.to.shared.u64 t, %1; cvt.u32.u64 %0, t; }" : "=r"(a) : "l"(p));
    return a;
}

__device__ __forceinline__ void cp16(uint32_t smem, const void* g) {
    asm volatile("cp.async.cg.shared.global [%0], [%1], 16;" :: "r"(smem), "l"(g));
}
#define CP_COMMIT() asm volatile("cp.async.commit_group;")
#define CP_WAIT(N)  asm volatile("cp.async.wait_group %0;" :: "n"(N))

// ---------------- float -> bf16 hi/lo conversion kernel ----------------
__global__ void k_cvt(const float* __restrict__ src, uint32_t* __restrict__ hi,
                      uint32_t* __restrict__ lo, int nw) {
    int i = blockIdx.x * blockDim.x + threadIdx.x;
    if (i >= nw) return;
    float2 v = reinterpret_cast<const float2*>(src)[i];
    uint32_t h, l;
    cvt_hl(v.x, v.y, h, l);
    hi[i] = h; lo[i] = l;
}

// ---------------- tensor-core bf16x3 GEMM v3 (cp.async 4-stage) ----------------
// C = act(A @ B^T). A/B hi/lo [rows, K/2 words]. M%128==0, N%128==0, K%16==0.
// 256 threads, warp tile 64x32 (2x4). Dynamic smem 4 stages x 24576 B.
template<int OUT>
__global__ __launch_bounds__(256)
void tc_gemm3(const uint32_t* __restrict__ Ah, const uint32_t* __restrict__ Al,
              const uint32_t* __restrict__ Bh, const uint32_t* __restrict__ Bl,
              float* __restrict__ C, uint32_t* __restrict__ Oh, uint32_t* __restrict__ Ol,
              int M, int N, int K)
{
    extern __shared__ uint32_t smem[];
    const uint32_t sb0 = smem_u32(smem);

    const int m0 = blockIdx.y * 128;
    const int n0 = blockIdx.x * 128;
    const int tid = threadIdx.x;
    const int wid = tid >> 5, lane = tid & 31;
    const int g = lane >> 2, tg = lane & 3;
    const int warp_m = wid >> 2, warp_n = wid & 3;
    const int wm0 = warp_m * 64, wn0 = warp_n * 32;
    const int K2 = K >> 1;

    const int rowa = tid >> 1, hw = (tid & 1) * 4;

    const int a_lrow = lane & 15;
    const int a_lcol = (lane >> 4) * 4;
    const int b_lrow = (lane & 7) + ((lane >> 4) << 3);
    const int b_lcol = ((lane >> 3) & 1) * 4;

    float acc[4][4][4];
    #pragma unroll
    for (int i = 0; i < 4; i++)
        #pragma unroll
        for (int j = 0; j < 4; j++)
            #pragma unroll
            for (int r = 0; r < 4; r++) acc[i][j][r] = 0.f;

    const int nk = K >> 4;

    // stage layout (bytes): ash +0, asl +6144, bsh +12288, bsl +18432; stage stride 24576
    const uint32_t dst_off = (uint32_t)(rowa * 12 + hw) * 4;
    const uint32_t* Ab = Ah + (size_t)(m0 + rowa) * K2 + hw;
    const uint32_t* Alb = Al + (size_t)(m0 + rowa) * K2 + hw;
    const uint32_t* Bb = Bh + (size_t)(n0 + rowa) * K2 + hw;
    const uint32_t* Blb = Bl + (size_t)(n0 + rowa) * K2 + hw;

    #define ISSUE(tile, stage) do {                              \
        uint32_t sb = sb0 + (stage) * 24576 + dst_off;           \
        int ko = (tile) * 8;                                     \
        cp16(sb,         Ab + ko);                               \
        cp16(sb + 6144,  Alb + ko);                              \
        cp16(sb + 12288, Bb + ko);                               \
        cp16(sb + 18432, Blb + ko);                              \
    } while (0)

    // prologue: tiles 0..2
    #pragma unroll
    for (int s = 0; s < 3; s++) {
        if (s < nk) ISSUE(s, s);
        CP_COMMIT();
    }

    for (int kt = 0; kt < nk; kt++) {
        if (kt + 3 < nk) ISSUE(kt + 3, (kt + 3) & 3);
        CP_COMMIT();
        CP_WAIT(3);
        __syncthreads();

        const uint32_t sb = sb0 + (kt & 3) * 24576;
        uint32_t ah[4][4], al[4][4], bh2[4][2], bl2[4][2];
        #pragma unroll
        for (int mi = 0; mi < 4; mi++) {
            uint32_t woff = (uint32_t)((wm0 + mi*16 + a_lrow) * 12 + a_lcol) * 4;
            ldsm4(ah[mi], sb + woff);
            ldsm4(al[mi], sb + 6144 + woff);
        }
        #pragma unroll
        for (int p = 0; p < 2; p++) {
            uint32_t woff = (uint32_t)((wn0 + p*16 + b_lrow) * 12 + b_lcol) * 4;
            uint32_t r[4];
            ldsm4(r, sb + 12288 + woff);
            bh2[2*p][0] = r[0]; bh2[2*p][1] = r[1];
            bh2[2*p+1][0] = r[2]; bh2[2*p+1][1] = r[3];
            ldsm4(r, sb + 18432 + woff);
            bl2[2*p][0] = r[0]; bl2[2*p][1] = r[1];
            bl2[2*p+1][0] = r[2]; bl2[2*p+1][1] = r[3];
        }
        #pragma unroll
        for (int mi = 0; mi < 4; mi++)
            #pragma unroll
            for (int ni = 0; ni < 4; ni++) {
                mma_bf16(acc[mi][ni], ah[mi], bh2[ni]);
                mma_bf16(acc[mi][ni], ah[mi], bl2[ni]);
                mma_bf16(acc[mi][ni], al[mi], bh2[ni]);
            }
        __syncthreads();
    }
    #undef ISSUE

    #pragma unroll
    for (int mi = 0; mi < 4; mi++) {
        #pragma unroll
        for (int ni = 0; ni < 4; ni++) {
            long long row0 = m0 + wm0 + mi * 16 + g;
            int col = n0 + wn0 + ni * 8 + tg * 2;
            if (OUT == 0) {
                *reinterpret_cast<float2*>(&C[row0 * N + col]) =
                    make_float2(acc[mi][ni][0], acc[mi][ni][1]);
                *reinterpret_cast<float2*>(&C[(row0 + 8) * N + col]) =
                    make_float2(acc[mi][ni][2], acc[mi][ni][3]);
            } else {
                float r[4];
                #pragma unroll
                for (int t = 0; t < 4; t++) {
                    float v = acc[mi][ni][t];
                    r[t] = 0.5f * v * (1.0f + erff(v * 0.70710678118654752f));
                }
                uint32_t h0, l0, h1, l1;
                cvt_hl(r[0], r[1], h0, l0);
                cvt_hl(r[2], r[3], h1, l1);
                size_t w0 = (size_t)(row0 * N + col) >> 1;
                size_t w1 = (size_t)((row0 + 8) * N + col) >> 1;
                Oh[w0] = h0; Ol[w0] = l0;
                Oh[w1] = h1; Ol[w1] = l1;
            }
        }
    }
}

// ---------------- fused flash attention (bf16x3, online softmax, prefetch) ----
#define FA_SK 36
__global__ __launch_bounds__(256)
void k_flash(const float* __restrict__ qp, const float* __restrict__ kp,
             const float* __restrict__ vpT, float* __restrict__ Og, int Tk)
{
    __shared__ uint32_t khw[64*FA_SK], klw[64*FA_SK];
    __shared__ uint32_t vhw[64*FA_SK], vlw[64*FA_SK];

    const int nh = blockIdx.y;
    const int q0 = blockIdx.x * 128;
    const int tid = threadIdx.x, wid = tid >> 5, lane = tid & 31;
    const int g = lane >> 2, tg = lane & 3;

    const float* Qb = qp + ((size_t)nh * LTOK + q0) * HD;
    const float* Kb = kp + (size_t)nh * Tk * HD;
    const float* Vb = vpT + (size_t)nh * HD * Tk;

    const int row0 = wid * 16 + g;
    uint32_t qh[4][4], ql[4][4];
    #pragma unroll
    for (int kk = 0; kk < 4; kk++) {
        int col = kk * 16 + tg * 2;
        float2 q00 = *reinterpret_cast<const float2*>(&Qb[(size_t)row0 * HD + col]);
        float2 q01 = *reinterpret_cast<const float2*>(&Qb[(size_t)row0 * HD + col + 8]);
        float2 q10 = *reinterpret_cast<const float2*>(&Qb[(size_t)(row0 + 8) * HD + col]);
        float2 q11 = *reinterpret_cast<const float2*>(&Qb[(size_t)(row0 + 8) * HD + col + 8]);
        cvt_hl(q00.x * 0.125f, q00.y * 0.125f, qh[kk][0], ql[kk][0]);
        cvt_hl(q10.x * 0.125f, q10.y * 0.125f, qh[kk][1], ql[kk][1]);
        cvt_hl(q01.x * 0.125f, q01.y * 0.125f, qh[kk][2], ql[kk][2]);
        cvt_hl(q11.x * 0.125f, q11.y * 0.125f, qh[kk][3], ql[kk][3]);
    }

    float m0 = -1e30f, m1 = -1e30f, l0 = 0.f, l1 = 0.f;
    float oacc[8][4];
    #pragma unroll
    for (int i = 0; i < 8; i++)
        #pragma unroll
        for (int t = 0; t < 4; t++) oacc[i][t] = 0.f;

    const int r = tid >> 2, c = (tid & 3) * 16;
    float4 rk[4], rv[4];
    {
        const float* sk = Kb + (size_t)r * HD + c;
        const float* sv = Vb + (size_t)r * Tk + c;
        #pragma unroll
        for (int j = 0; j < 4; j++) {
            rk[j] = *reinterpret_cast<const float4*>(sk + j * 4);
            rv[j] = *reinterpret_cast<const float4*>(sv + j * 4);
        }
    }

    for (int kv0 = 0; kv0 < Tk; kv0 += 64) {
        // store current chunk (registers) into smem with hi/lo split
        #pragma unroll
        for (int j = 0; j < 4; j++) {
            int w = r * FA_SK + (c >> 1) + j * 2;
            uint32_t h, l;
            cvt_hl(rk[j].x, rk[j].y, h, l); khw[w] = h;   klw[w] = l;
            cvt_hl(rk[j].z, rk[j].w, h, l); khw[w+1] = h; klw[w+1] = l;
            cvt_hl(rv[j].x, rv[j].y, h, l); vhw[w] = h;   vlw[w] = l;
            cvt_hl(rv[j].z, rv[j].w, h, l); vhw[w+1] = h; vlw[w+1] = l;
        }
        __syncthreads();

        // prefetch next chunk while computing this one
        if (kv0 + 64 < Tk) {
            const float* sk = Kb + (size_t)(kv0 + 64 + r) * HD + c;
            const float* sv = Vb + (size_t)r * Tk + (kv0 + 64) + c;
            #pragma unroll
            for (int j = 0; j < 4; j++) {
                rk[j] = *reinterpret_cast<const float4*>(sk + j * 4);
                rv[j] = *reinterpret_cast<const float4*>(sv + j * 4);
            }
        }

        float sacc[8][4];
        #pragma unroll
        for (int i = 0; i < 8; i++)
            #pragma unroll
            for (int t = 0; t < 4; t++) sacc[i][t] = 0.f;
        #pragma unroll
        for (int kk = 0; kk < 4; kk++) {
            #pragma unroll
            for (int ni = 0; ni < 8; ni++) {
                uint32_t bh[2], bl[2];
                int off = (ni * 8 + g) * FA_SK + kk * 8 + tg;
                bh[0] = khw[off]; bh[1] = khw[off + 4];
                bl[0] = klw[off]; bl[1] = klw[off + 4];
                mma_bf16(sacc[ni], qh[kk], bh);
                mma_bf16(sacc[ni], qh[kk], bl);
                mma_bf16(sacc[ni], ql[kk], bh);
            }
        }

        float mx0 = -1e30f, mx1 = -1e30f;
        #pragma unroll
        for (int ni = 0; ni < 8; ni++) {
            mx0 = fmaxf(mx0, fmaxf(sacc[ni][0], sacc[ni][1]));
            mx1 = fmaxf(mx1, fmaxf(sacc[ni][2], sacc[ni][3]));
        }
        mx0 = fmaxf(mx0, __shfl_xor_sync(0xffffffff, mx0, 1));
        mx0 = fmaxf(mx0, __shfl_xor_sync(0xffffffff, mx0, 2));
        mx1 = fmaxf(mx1, __shfl_xor_sync(0xffffffff, mx1, 1));
        mx1 = fmaxf(mx1, __shfl_xor_sync(0xffffffff, mx1, 2));
        float nm0 = fmaxf(m0, mx0), nm1 = fmaxf(m1, mx1);
        float al0 = __expf(m0 - nm0), al1 = __expf(m1 - nm1);
        float rs0 = 0.f, rs1 = 0.f;
        #pragma unroll
        for (int ni = 0; ni < 8; ni++) {
            sacc[ni][0] = __expf(sacc[ni][0] - nm0);
            sacc[ni][1] = __expf(sacc[ni][1] - nm0);
            sacc[ni][2] = __expf(sacc[ni][2] - nm1);
            sacc[ni][3] = __expf(sacc[ni][3] - nm1);
            rs0 += sacc[ni][0] + sacc[ni][1];
            rs1 += sacc[ni][2] + sacc[ni][3];
        }
        rs0 += __shfl_xor_sync(0xffffffff, rs0, 1);
        rs0 += __shfl_xor_sync(0xffffffff, rs0, 2);
        rs1 += __shfl_xor_sync(0xffffffff, rs1, 1);
        rs1 += __shfl_xor_sync(0xffffffff, rs1, 2);
        l0 = l0 * al0 + rs0;  l1 = l1 * al1 + rs1;
        m0 = nm0;  m1 = nm1;
        #pragma unroll
        for (int nd = 0; nd < 8; nd++) {
            oacc[nd][0] *= al0; oacc[nd][1] *= al0;
            oacc[nd][2] *= al1; oacc[nd][3] *= al1;
        }

        #pragma unroll
        for (int kk = 0; kk < 4; kk++) {
            uint32_t ph[4], pl[4];
            cvt_hl(sacc[2*kk][0],   sacc[2*kk][1],   ph[0], pl[0]);
            cvt_hl(sacc[2*kk][2],   sacc[2*kk][3],   ph[1], pl[1]);
            cvt_hl(sacc[2*kk+1][0], sacc[2*kk+1][1], ph[2], pl[2]);
            cvt_hl(sacc[2*kk+1][2], sacc[2*kk+1][3], ph[3], pl[3]);
            #pragma unroll
            for (int nd = 0; nd < 8; nd++) {
                uint32_t vh[2], vl[2];
                int off = (nd * 8 + g) * FA_SK + kk * 8 + tg;
                vh[0] = vhw[off]; vh[1] = vhw[off + 4];
                vl[0] = vlw[off]; vl[1] = vlw[off + 4];
                mma_bf16(oacc[nd], ph, vh);
                mma_bf16(oacc[nd], ph, vl);
                mma_bf16(oacc[nd], pl, vh);
            }
        }
        __syncthreads();
    }

    float il0 = 1.0f / l0, il1 = 1.0f / l1;
    float* Ob = Og + ((size_t)nh * LTOK + q0) * HD;
    #pragma unroll
    for (int nd = 0; nd < 8; nd++) {
        int col = nd * 8 + tg * 2;
        *reinterpret_cast<float2*>(&Ob[(size_t)row0 * HD + col]) =
            make_float2(oacc[nd][0] * il0, oacc[nd][1] * il0);
        *reinterpret_cast<float2*>(&Ob[(size_t)(row0 + 8) * HD + col]) =
            make_float2(oacc[nd][2] * il1, oacc[nd][3] * il1);
    }
}

// ---------------- layout kernels ----------------
__global__ void k_build_x(const float* __restrict__ f, float* __restrict__ x,
                          uint32_t* __restrict__ xh, uint32_t* __restrict__ xl) {
    int idx = blockIdx.x * blockDim.x + threadIdx.x;
    if (idx >= XW) return;
    int c2 = idx & 127;
    int l  = (idx >> 7) & (LTOK-1);
    int n  = idx >> 17;
    int c  = c2 * 2;
    float a = f[((size_t)n*CC + c)*LTOK + l];
    float b = f[((size_t)n*CC + c + 1)*LTOK + l];
    reinterpret_cast<float2*>(x)[idx] = make_float2(a, b);
    uint32_t h, lw;
    cvt_hl(a, b, h, lw);
    xh[idx] = h; xl[idx] = lw;
}

__global__ void k_final(const float* __restrict__ x, float* __restrict__ o) {
    int idx = blockIdx.x * blockDim.x + threadIdx.x;
    if (idx >= ROWS_*CC) return;
    int l = idx & (LTOK-1);
    int c = (idx >> 10) & (CC-1);
    int n = idx >> 18;
    o[idx] = x[((size_t)n*LTOK + l)*CC + c];
}

// ---------------- PRoPE matrix build ----------------
__device__ __forceinline__ void prope_forward(const float* vm, const float* Kc,
                                              float u, float vyy, float* M) {
    float fx = Kc[0] * (1.0f/128.0f), fy = Kc[4] * (1.0f/128.0f);
    float cx = Kc[2] * (1.0f/128.0f), cy = Kc[5] * (1.0f/128.0f);
    float a = cx - u, b = cy - vyy;
    #pragma unroll
    for (int c = 0; c < 4; c++) {
        M[0*4+c] = fx*vm[0*4+c] + a*vm[2*4+c];
        M[1*4+c] = fy*vm[1*4+c] + b*vm[2*4+c];
        M[2*4+c] = vm[2*4+c];
        M[3*4+c] = vm[3*4+c];
    }
}

__global__ void k_prope_q(const float* __restrict__ vms, const float* __restrict__ Ks,
                          float* __restrict__ Mq, float* __restrict__ Mqi) {
    int idx = blockIdx.x * blockDim.x + threadIdx.x;
    if (idx >= NVB*LTOK) return;
    int n = idx >> 10, t = idx & (LTOK-1);
    int px = t & 31, py = t >> 5;
    float u  = (px + 0.5f) * (1.0f/32.0f);
    float vy = (py + 0.5f) * (1.0f/32.0f);
    const float* vm = vms + n*16;
    const float* Kc = Ks + n*9;
    float M[16];
    prope_forward(vm, Kc, u, vy, M);
    #pragma unroll
    for (int i = 0; i < 16; i++) Mq[idx*16+i] = M[i];

    float r00=vm[0],r01=vm[1],r02=vm[2],  t0=vm[3];
    float r10=vm[4],r11=vm[5],r12=vm[6],  t1=vm[7];
    float r20=vm[8],r21=vm[9],r22=vm[10], t2=vm[11];
    float det = r00*(r11*r22-r12*r21) - r01*(r10*r22-r12*r20) + r02*(r10*r21-r11*r20);
    float id = 1.0f/det;
    float Ri[9];
    Ri[0]=(r11*r22-r12*r21)*id; Ri[1]=(r02*r21-r01*r22)*id; Ri[2]=(r01*r12-r02*r11)*id;
    Ri[3]=(r12*r20-r10*r22)*id; Ri[4]=(r00*r22-r02*r20)*id; Ri[5]=(r02*r10-r00*r12)*id;
    Ri[6]=(r10*r21-r11*r20)*id; Ri[7]=(r01*r20-r00*r21)*id; Ri[8]=(r00*r11-r01*r10)*id;
    float ti0 = -(Ri[0]*t0 + Ri[1]*t1 + Ri[2]*t2);
    float ti1 = -(Ri[3]*t0 + Ri[4]*t1 + Ri[5]*t2);
    float ti2 = -(Ri[6]*t0 + Ri[7]*t1 + Ri[8]*t2);
    float fx = Kc[0]*(1.0f/128.0f), fy = Kc[4]*(1.0f/128.0f);
    float cx = Kc[2]*(1.0f/128.0f), cy = Kc[5]*(1.0f/128.0f);
    float a = cx - u, b = cy - vy;
    float ifx = 1.0f/fx, ify = 1.0f/fy;
    float Mi[16];
    float tv[3] = {ti0, ti1, ti2};
    #pragma unroll
    for (int i = 0; i < 3; i++) {
        Mi[i*4+0] = Ri[i*3+0]*ifx;
        Mi[i*4+1] = Ri[i*3+1]*ify;
        Mi[i*4+2] = -Ri[i*3+0]*a*ifx - Ri[i*3+1]*b*ify + Ri[i*3+2];
        Mi[i*4+3] = tv[i];
    }
    Mi[12]=0.f; Mi[13]=0.f; Mi[14]=0.f; Mi[15]=1.f;
    #pragma unroll
    for (int i = 0; i < 16; i++) Mqi[idx*16+i] = Mi[i];
}

__global__ void k_prope_kv(const float* __restrict__ vms, const float* __restrict__ Ks,
                           float* __restrict__ Mkv) {
    int idx = blockIdx.x * blockDim.x + threadIdx.x;
    if (idx >= NVB*TKX) return;
    int n = idx >> 11, tt = idx & (TKX-1);
    int m = tt >> 10, l = tt & (LTOK-1);
    int vvi = n >> 1, b = n & 1;
    int j = m + (m >= vvi ? 1 : 0);
    int cam = j*BB + b;
    int px = l & 31, py = l >> 5;
    float u  = (px + 0.5f)*(1.0f/32.0f);
    float vy = (py + 0.5f)*(1.0f/32.0f);
    float M[16];
    prope_forward(vms + cam*16, Ks + cam*9, u, vy, M);
    #pragma unroll
    for (int i = 0; i < 16; i++) Mkv[idx*16+i] = M[i];
}

// ---------------- per-token 4x4 projective applies (strided sources) ---------
__global__ void k_apply_q(const float* __restrict__ q, int stride,
                          const float* __restrict__ Mi, float* __restrict__ qp) {
    int idx = blockIdx.x * blockDim.x + threadIdx.x;
    if (idx >= NVB*LTOK*NH*16) return;
    int g = idx & 15, h = (idx >> 4) & 3, t = (idx >> 6) & (LTOK-1), n = idx >> 16;
    const float* M = Mi + ((size_t)(n*LTOK + t))*16;
    const float* s = q + ((size_t)(n*LTOK + t))*stride + h*HD + g*4;
    float x0=s[0], x1=s[1], x2=s[2], x3=s[3];
    float* d = qp + (((size_t)(n*NH + h))*LTOK + t)*HD + g*4;
    #pragma unroll
    for (int i = 0; i < 4; i++)
        d[i] = M[0*4+i]*x0 + M[1*4+i]*x1 + M[2*4+i]*x2 + M[3*4+i]*x3;
}

__global__ void k_apply_kv(const float* __restrict__ ks, int stride,
                           const float* __restrict__ Mats,
                           float* __restrict__ kp, int Tk, int gather) {
    int idx = blockIdx.x * blockDim.x + threadIdx.x;
    if (idx >= NVB*Tk*NH*16) return;
    int g = idx & 15, h = (idx >> 4) & 3;
    int tt = (idx >> 6) % Tk, n = (idx >> 6) / Tk;
    size_t srcRow;
    if (gather) {
        int m = tt >> 10, l = tt & (LTOK-1);
        int vvi = n >> 1, b = n & 1;
        int j = m + (m >= vvi ? 1 : 0);
        srcRow = (size_t)(j*BB + b)*LTOK + l;
    } else {
        srcRow = (size_t)n*LTOK + tt;
    }
    const float* M = Mats + ((size_t)n*Tk + tt)*16;
    const float* s = ks + srcRow*stride + h*HD + g*4;
    float x0=s[0], x1=s[1], x2=s[2], x3=s[3];
    float* d = kp + (((size_t)(n*NH + h))*Tk + tt)*HD + g*4;
    #pragma unroll
    for (int i = 0; i < 4; i++)
        d[i] = M[i*4+0]*x0 + M[i*4+1]*x1 + M[i*4+2]*x2 + M[i*4+3]*x3;
}

__global__ void k_apply_v_t(const float* __restrict__ vs, int stride,
                            const float* __restrict__ Mats,
                            float* __restrict__ vpT, int Tk, int gather) {
    int idx = blockIdx.x * blockDim.x + threadIdx.x;
    if (idx >= NVB*NH*16*Tk) return;
    int tt = idx % Tk;
    int rest = idx / Tk;
    int g = rest & 15, h = (rest >> 4) & 3, n = rest >> 6;
    size_t srcRow;
    if (gather) {
        int m = tt >> 10, l = tt & (LTOK-1);
        int vvi = n >> 1, b = n & 1;
        int j = m + (m >= vvi ? 1 : 0);
        srcRow = (size_t)(j*BB + b)*LTOK + l;
    } else {
        srcRow = (size_t)n*LTOK + tt;
    }
    const float* M = Mats + ((size_t)n*Tk + tt)*16;
    const float* s = vs + srcRow*stride + h*HD + g*4;
    float x0=s[0], x1=s[1], x2=s[2], x3=s[3];
    float* dbase = vpT + ((size_t)(n*NH + h)*HD + g*4)*Tk + tt;
    #pragma unroll
    for (int i = 0; i < 4; i++)
        dbase[(size_t)i*Tk] = M[i*4+0]*x0 + M[i*4+1]*x1 + M[i*4+2]*x2 + M[i*4+3]*x3;
}

__global__ void k_apply_out(const float* __restrict__ O, const float* __restrict__ Mi,
                            uint32_t* __restrict__ omh, uint32_t* __restrict__ oml) {
    int idx = blockIdx.x * blockDim.x + threadIdx.x;
    if (idx >= NVB*LTOK*NH*16) return;
    int g = idx & 15, h = (idx >> 4) & 3, t = (idx >> 6) & (LTOK-1), n = idx >> 16;
    const float* M = Mi + ((size_t)(n*LTOK + t))*16;
    const float* s = O + (((size_t)(n*NH + h))*LTOK + t)*HD + g*4;
    float x0=s[0], x1=s[1], x2=s[2], x3=s[3];
    float d[4];
    #pragma unroll
    for (int i = 0; i < 4; i++)
        d[i] = M[i*4+0]*x0 + M[i*4+1]*x1 + M[i*4+2]*x2 + M[i*4+3]*x3;
    size_t w = (((size_t)(n*LTOK + t))*CC + h*HD + g*4) >> 1;
    uint32_t h0, l0, h1, l1;
    cvt_hl(d[0], d[1], h0, l0);
    cvt_hl(d[2], d[3], h1, l1);
    omh[w] = h0;   oml[w] = l0;
    omh[w+1] = h1; oml[w+1] = l1;
}

// ---------------- layernorm ----------------
__global__ void k_ln(float* __restrict__ dst, const float* __restrict__ src,
                     const float* __restrict__ w, const float* __restrict__ b, int add,
                     uint32_t* __restrict__ oh, uint32_t* __restrict__ ol) {
    __shared__ float red[256];
    int row = blockIdx.x, tid = threadIdx.x;
    float v = src[(size_t)row*CC + tid];
    red[tid] = v; __syncthreads();
    for (int s = 128; s > 0; s >>= 1) { if (tid < s) red[tid] += red[tid+s]; __syncthreads(); }
    float mu = red[0] * (1.0f/CC); __syncthreads();
    float d = v - mu;
    red[tid] = d * d; __syncthreads();
    for (int s = 128; s > 0; s >>= 1) { if (tid < s) red[tid] += red[tid+s]; __syncthreads(); }
    float var = red[0] * (1.0f/CC);
    float o = d * rsqrtf(var + 1e-5f) * w[tid] + b[tid];
    float fin;
    if (add) { fin = dst[(size_t)row*CC + tid] + o; dst[(size_t)row*CC + tid] = fin; }
    else     { fin = o; dst[(size_t)row*CC + tid] = fin; }
    if (oh) {
        __syncthreads();
        red[tid] = fin;
        __syncthreads();
        if (tid < 128) {
            uint32_t h, l;
            cvt_hl(red[2*tid], red[2*tid+1], h, l);
            oh[(size_t)row*(CC/2) + tid] = h;
            ol[(size_t)row*(CC/2) + tid] = l;
        }
    }
}

// ---------------- concat -> bf16 hi/lo ----------------
__global__ void k_cat(const float* __restrict__ x, const float* __restrict__ msg,
                      uint32_t* __restrict__ ch, uint32_t* __restrict__ cl) {
    int idx = blockIdx.x * blockDim.x + threadIdx.x;
    if (idx >= ROWS_*(FFNI/2)) return;
    int c2 = idx & 255, row = idx >> 8;
    float2 v;
    if (c2 < 128) v = reinterpret_cast<const float2*>(x + (size_t)row*CC)[c2];
    else          v = reinterpret_cast<const float2*>(msg + (size_t)row*CC)[c2 - 128];
    uint32_t h, l;
    cvt_hl(v.x, v.y, h, l);
    ch[idx] = h; cl[idx] = l;
}

// ---------------- host driver ----------------
static const int GSMEM = 98304;   // 4 stages x 24576 B

static void gemm3(const uint32_t* Ah, const uint32_t* Al,
                  const uint32_t* Bh, const uint32_t* Bl,
                  float* C, int M, int N, int K) {
    dim3 g(N/128, M/128);
    tc_gemm3<0><<<g, 256, GSMEM>>>(Ah, Al, Bh, Bl, C, nullptr, nullptr, M, N, K);
}
static void gemm3_gelu_hl(const uint32_t* Ah, const uint32_t* Al,
                          const uint32_t* Bh, const uint32_t* Bl,
                          uint32_t* Oh, uint32_t* Ol, int M, int N, int K) {
    dim3 g(N/128, M/128);
    tc_gemm3<1><<<g, 256, GSMEM>>>(Ah, Al, Bh, Bl, nullptr, Oh, Ol, M, N, K);
}

extern "C" void kernel_launch(void* const* d_in, const int* in_sizes, int n_in,
                              void* d_out, int out_size) {
    const float* feats = (const float*)d_in[0];
    const float* vms   = (const float*)d_in[1];
    const float* Ks    = (const float*)d_in[2];
    const float* Wq    = (const float*)d_in[3];
    const float* Wk    = (const float*)d_in[4];
    const float* Wv    = (const float*)d_in[5];
    const float* Wm    = (const float*)d_in[6];
    const float* n1w   = (const float*)d_in[7];
    const float* n1b   = (const float*)d_in[8];
    const float* W1    = (const float*)d_in[9];
    const float* W2    = (const float*)d_in[10];
    const float* n2w   = (const float*)d_in[11];
    const float* n2b   = (const float*)d_in[12];

    cudaFuncSetAttribute(tc_gemm3<0>, cudaFuncAttributeMaxDynamicSharedMemorySize, GSMEM);
    cudaFuncSetAttribute(tc_gemm3<1>, cudaFuncAttributeMaxDynamicSharedMemorySize, GSMEM);

    void* p;
    float *x,*qkv,*q,*kvb,*qp,*kp,*vp,*O,*msg,*h2,*Mq,*Mqi,*Mkv;
    uint32_t *xh,*xl,*xpreh,*xprel,*omh,*oml,*cath,*catl,*hh,*hl,*wh,*wl;
    cudaGetSymbolAddress(&p, g_x);    x   = (float*)p;
    cudaGetSymbolAddress(&p, g_qkv);  qkv = (float*)p;
    cudaGetSymbolAddress(&p, g_q);    q   = (float*)p;
    cudaGetSymbolAddress(&p, g_kvb);  kvb = (float*)p;
    cudaGetSymbolAddress(&p, g_qp);   qp  = (float*)p;
    cudaGetSymbolAddress(&p, g_kp);   kp  = (float*)p;
    cudaGetSymbolAddress(&p, g_vp);   vp  = (float*)p;
    cudaGetSymbolAddress(&p, g_O);    O   = (float*)p;
    cudaGetSymbolAddress(&p, g_msg);  msg = (float*)p;
    cudaGetSymbolAddress(&p, g_h2);   h2  = (float*)p;
    cudaGetSymbolAddress(&p, g_Mq);   Mq  = (float*)p;
    cudaGetSymbolAddress(&p, g_Mqi);  Mqi = (float*)p;
    cudaGetSymbolAddress(&p, g_Mkv);  Mkv = (float*)p;
    cudaGetSymbolAddress(&p, g_xh);    xh    = (uint32_t*)p;
    cudaGetSymbolAddress(&p, g_xl);    xl    = (uint32_t*)p;
    cudaGetSymbolAddress(&p, g_xpreh); xpreh = (uint32_t*)p;
    cudaGetSymbolAddress(&p, g_xprel); xprel = (uint32_t*)p;
    cudaGetSymbolAddress(&p, g_omh);   omh   = (uint32_t*)p;
    cudaGetSymbolAddress(&p, g_oml);   oml   = (uint32_t*)p;
    cudaGetSymbolAddress(&p, g_cath);  cath  = (uint32_t*)p;
    cudaGetSymbolAddress(&p, g_catl);  catl  = (uint32_t*)p;
    cudaGetSymbolAddress(&p, g_hh);    hh    = (uint32_t*)p;
    cudaGetSymbolAddress(&p, g_hl);    hl    = (uint32_t*)p;
    cudaGetSymbolAddress(&p, g_wh);    wh    = (uint32_t*)p;
    cudaGetSymbolAddress(&p, g_wl);    wl    = (uint32_t*)p;

    const int ROWS = ROWS_;
    const int NEL  = ROWS * CC;

    // weight preconversion / repack (offsets in words; sources in floats)
    for (int ly = 0; ly < 2; ly++) {
        size_t s0 = (size_t)(ly*2+0) * 65536;   // floats
        size_t s1 = (size_t)(ly*2+1) * 65536;
        uint32_t dq = WQKV0 + ly*98304;
        k_cvt<<<128, 256>>>(Wq + s0, wh+dq,        wl+dq,        32768);
        k_cvt<<<128, 256>>>(Wk + s0, wh+dq+32768,  wl+dq+32768,  32768);
        k_cvt<<<128, 256>>>(Wv + s0, wh+dq+65536,  wl+dq+65536,  32768);
        k_cvt<<<128, 256>>>(Wq + s1, wh+WQX0+ly*32768, wl+WQX0+ly*32768, 32768);
        uint32_t dk = WKVX0 + ly*65536;
        k_cvt<<<128, 256>>>(Wk + s1, wh+dk,        wl+dk,        32768);
        k_cvt<<<128, 256>>>(Wv + s1, wh+dk+32768,  wl+dk+32768,  32768);
    }
    k_cvt<<<512, 256>>>(Wm, wh+WMO, wl+WMO, 131072);
    k_cvt<<<4096, 256>>>(W1, wh+W1O, wl+W1O, 1048576);
    k_cvt<<<2048, 256>>>(W2, wh+W2O, wl+W2O, 524288);

    k_build_x<<<(XW+255)/256, 256>>>(feats, x, xh, xl);
    k_prope_q<<<(ROWS+255)/256, 256>>>(vms, Ks, Mq, Mqi);
    k_prope_kv<<<(NVB*TKX+255)/256, 256>>>(vms, Ks, Mkv);

    for (int ly = 0; ly < 2; ly++) {
        // snapshot x (pre-self-attn) for cross-attn KV
        k_cvt<<<(XW+255)/256, 256>>>(x, xpreh, xprel, XW);

        // ---------- self attention (fused QKV, N=768) ----------
        gemm3(xh, xl, wh+WQKV0+ly*98304, wl+WQKV0+ly*98304, qkv, ROWS, 768, CC);
        k_apply_q  <<<(NVB*LTOK*NH*16)/256, 256>>>(qkv + 0,   768, Mqi, qp);
        k_apply_kv <<<(NVB*LTOK*NH*16)/256, 256>>>(qkv + 256, 768, Mq, kp, LTOK, 0);
        k_apply_v_t<<<(NVB*LTOK*NH*16)/256, 256>>>(qkv + 512, 768, Mq, vp, LTOK, 0);
        k_flash<<<dim3(LTOK/128, NVB*NH), 256>>>(qp, kp, vp, O, LTOK);
        k_apply_out<<<(NVB*LTOK*NH*16)/256, 256>>>(O, Mqi, omh, oml);
        gemm3(omh, oml, wh+WMO+(ly*2+0)*32768, wl+WMO+(ly*2+0)*32768, msg, ROWS, CC, CC);
        k_ln<<<ROWS, 256>>>(x, msg, n1w + (ly*2+0)*CC, n1b + (ly*2+0)*CC, 1, xh, xl);

        // ---------- cross attention (Q N=256; fused KV N=512) ----------
        gemm3(xh, xl, wh+WQX0+ly*32768, wl+WQX0+ly*32768, q, ROWS, CC, CC);
        gemm3(xpreh, xprel, wh+WKVX0+ly*65536, wl+WKVX0+ly*65536, kvb, ROWS, 512, CC);
        k_apply_q  <<<(NVB*LTOK*NH*16)/256, 256>>>(q, 256, Mqi, qp);
        k_apply_kv <<<(NVB*TKX*NH*16)/256, 256>>>(kvb + 0,   512, Mkv, kp, TKX, 1);
        k_apply_v_t<<<(NVB*TKX*NH*16)/256, 256>>>(kvb + 256, 512, Mkv, vp, TKX, 1);
        k_flash<<<dim3(LTOK/128, NVB*NH), 256>>>(qp, kp, vp, O, TKX);
        k_apply_out<<<(NVB*LTOK*NH*16)/256, 256>>>(O, Mqi, omh, oml);
        gemm3(omh, oml, wh+WMO+(ly*2+1)*32768, wl+WMO+(ly*2+1)*32768, msg, ROWS, CC, CC);
        k_ln<<<ROWS, 256>>>(msg, msg, n1w + (ly*2+1)*CC, n1b + (ly*2+1)*CC, 0,
                            nullptr, nullptr);

        // ---------- FFN ----------
        k_cat<<<(ROWS*(FFNI/2))/256, 256>>>(x, msg, cath, catl);
        gemm3_gelu_hl(cath, catl, wh+W1O + (size_t)ly*524288, wl+W1O + (size_t)ly*524288,
                      hh, hl, ROWS, FFNH, FFNI);
        gemm3(hh, hl, wh+W2O + (size_t)ly*262144, wl+W2O + (size_t)ly*262144,
              h2, ROWS, CC, FFNH);
        k_ln<<<ROWS, 256>>>(x, h2, n2w + ly*CC, n2b + ly*CC, 1, xh, xl);
    }

    k_final<<<(NEL+255)/256, 256>>>(x, (float*)d_out);
}